// round 1
// baseline (speedup 1.0000x reference)
#include <cuda_runtime.h>
#include <cuda_bf16.h>
#include <math.h>

// Problem constants
#define BB   2
#define SS   2048
#define DIN  1024
#define DD   1024
#define HH   16
#define HDIM 64
#define M_ROWS (BB * SS)      // 4096
#define QKV_N  (3 * DD)       // 3072

// Scratch (static device globals — no runtime allocation allowed)
__device__ float g_qkv [M_ROWS * QKV_N];  // [B*S, 3072], head-major packing [H, 3*HD]
__device__ float g_vals[M_ROWS * DD];     // attention output, [B*S, H*HD]

// ---------------------------------------------------------------------------
// SGEMM: C[M,N] = A[M,K] @ Bw[N,K]^T + bias[N]
// 128x128 block tile, BK=8, 256 threads, 8x8 per-thread micro-tile.
// Requires M,N multiples of 128, K multiple of 8 (true for all our shapes).
// ---------------------------------------------------------------------------
__global__ __launch_bounds__(256) void sgemm_kernel(
    const float* __restrict__ A, const float* __restrict__ Bw,
    const float* __restrict__ bias, float* __restrict__ C,
    int M, int N, int K)
{
    __shared__ float As[8][128];
    __shared__ float Bs[8][128];

    const int tid = threadIdx.x;
    const int m0 = blockIdx.y * 128;
    const int n0 = blockIdx.x * 128;

    const int lrow = tid >> 1;           // 0..127, row within tile for loading
    const int lseg = (tid & 1) * 4;      // 0 or 4, k-segment for loading

    const float* Aptr = A + (size_t)(m0 + lrow) * K + lseg;
    const float* Bptr = Bw + (size_t)(n0 + lrow) * K + lseg;

    const int ty = tid >> 4;             // 0..15
    const int tx = tid & 15;             // 0..15
    const int rb = ty * 8;
    const int cb = tx * 8;

    float acc[8][8];
#pragma unroll
    for (int i = 0; i < 8; i++)
#pragma unroll
        for (int j = 0; j < 8; j++) acc[i][j] = 0.f;

    for (int k0 = 0; k0 < K; k0 += 8) {
        float4 av = *(const float4*)(Aptr + k0);
        float4 bv = *(const float4*)(Bptr + k0);
        __syncthreads();   // protect previous iteration's reads
        As[lseg + 0][lrow] = av.x;
        As[lseg + 1][lrow] = av.y;
        As[lseg + 2][lrow] = av.z;
        As[lseg + 3][lrow] = av.w;
        Bs[lseg + 0][lrow] = bv.x;
        Bs[lseg + 1][lrow] = bv.y;
        Bs[lseg + 2][lrow] = bv.z;
        Bs[lseg + 3][lrow] = bv.w;
        __syncthreads();

#pragma unroll
        for (int kk = 0; kk < 8; kk++) {
            float a[8], b[8];
            *(float4*)(a)     = *(const float4*)&As[kk][rb];
            *(float4*)(a + 4) = *(const float4*)&As[kk][rb + 4];
            *(float4*)(b)     = *(const float4*)&Bs[kk][cb];
            *(float4*)(b + 4) = *(const float4*)&Bs[kk][cb + 4];
#pragma unroll
            for (int i = 0; i < 8; i++)
#pragma unroll
                for (int j = 0; j < 8; j++)
                    acc[i][j] += a[i] * b[j];
        }
    }

    // Epilogue: add bias, store vectorized
#pragma unroll
    for (int i = 0; i < 8; i++) {
        float* crow = C + (size_t)(m0 + rb + i) * N + n0 + cb;
#pragma unroll
        for (int j4 = 0; j4 < 8; j4 += 4) {
            float4 o;
            o.x = acc[i][j4 + 0] + bias[n0 + cb + j4 + 0];
            o.y = acc[i][j4 + 1] + bias[n0 + cb + j4 + 1];
            o.z = acc[i][j4 + 2] + bias[n0 + cb + j4 + 2];
            o.w = acc[i][j4 + 3] + bias[n0 + cb + j4 + 3];
            *(float4*)(crow + j4) = o;
        }
    }
}

// ---------------------------------------------------------------------------
// Flash attention, fp32. One thread owns one query row (q + acc in registers).
// Block = 128 threads = 128 query rows. K/V tiles of 64 rows in shared memory.
// Grid: (S/128, H, B).
// qkv layout per row: [H][3*HD] -> q at h*192, k at h*192+64, v at h*192+128.
// ---------------------------------------------------------------------------
#define ATT_SMEM_FLOATS (4096 + 4096 + 128 * 65)
#define ATT_SMEM_BYTES  (ATT_SMEM_FLOATS * 4)

__global__ __launch_bounds__(128) void attn_kernel(
    const float* __restrict__ qkv, float* __restrict__ vals)
{
    extern __shared__ float smem[];
    float* k_s = smem;           // 64 x 64
    float* v_s = smem + 4096;    // 64 x 64
    float* p_s = smem + 8192;    // 128 x 65 (padded: conflict-free per-thread rows)

    const int tid = threadIdx.x;
    const int b = blockIdx.z;
    const int h = blockIdx.y;
    const int q0 = blockIdx.x * 128;
    const float scale = 0.125f;  // 1/sqrt(64)

    // Load this thread's q row into registers
    const float* qptr = qkv + (size_t)(b * SS + q0 + tid) * QKV_N + h * 192;
    float q[64];
#pragma unroll
    for (int d = 0; d < 64; d += 4)
        *(float4*)&q[d] = *(const float4*)(qptr + d);

    float m_i = -1e30f, l_i = 0.f;
    float acc[64];
#pragma unroll
    for (int d = 0; d < 64; d++) acc[d] = 0.f;

    const float* kbase = qkv + (size_t)(b * SS) * QKV_N + h * 192 + 64;
    float* prow = p_s + tid * 65;

    for (int kt = 0; kt < SS / 64; kt++) {
        // Cooperative load of K and V tiles (64 rows x 64 cols, coalesced float4)
        const float* kt_ptr = kbase + (size_t)kt * 64 * QKV_N;
#pragma unroll
        for (int i = tid; i < 64 * 16; i += 128) {
            int r = i >> 4;
            int c = (i & 15) << 2;
            *(float4*)&k_s[r * 64 + c] = *(const float4*)(kt_ptr + (size_t)r * QKV_N + c);
            *(float4*)&v_s[r * 64 + c] = *(const float4*)(kt_ptr + (size_t)r * QKV_N + 64 + c);
        }
        __syncthreads();

        // Scores for this tile (k_s reads are warp-broadcast: conflict-free)
        float tmax = -1e30f;
#pragma unroll 4
        for (int j = 0; j < 64; j++) {
            const float* kr = k_s + j * 64;
            float s = 0.f;
#pragma unroll
            for (int d = 0; d < 64; d += 4) {
                float4 kv = *(const float4*)(kr + d);
                s += q[d] * kv.x + q[d + 1] * kv.y + q[d + 2] * kv.z + q[d + 3] * kv.w;
            }
            s *= scale;
            prow[j] = s;
            tmax = fmaxf(tmax, s);
        }

        // Online softmax rescale
        float m_new = fmaxf(m_i, tmax);
        float corr = __expf(m_i - m_new);
        l_i *= corr;
#pragma unroll
        for (int d = 0; d < 64; d++) acc[d] *= corr;
        m_i = m_new;

        // P @ V accumulation (v_s reads are warp-broadcast)
#pragma unroll 2
        for (int j = 0; j < 64; j++) {
            float p = __expf(prow[j] - m_new);
            l_i += p;
            const float* vr = v_s + j * 64;
#pragma unroll
            for (int d = 0; d < 64; d += 4) {
                float4 vv = *(const float4*)(vr + d);
                acc[d]     += p * vv.x;
                acc[d + 1] += p * vv.y;
                acc[d + 2] += p * vv.z;
                acc[d + 3] += p * vv.w;
            }
        }
        __syncthreads();
    }

    // Normalize and write out: vals[b, s, h*HD + d]
    const float inv = 1.f / l_i;
    float* optr = vals + (size_t)(b * SS + q0 + tid) * DD + h * HDIM;
#pragma unroll
    for (int d = 0; d < 64; d += 4) {
        float4 o;
        o.x = acc[d] * inv;
        o.y = acc[d + 1] * inv;
        o.z = acc[d + 2] * inv;
        o.w = acc[d + 3] * inv;
        *(float4*)(optr + d) = o;
    }
}

// ---------------------------------------------------------------------------
// Launch
// ---------------------------------------------------------------------------
extern "C" void kernel_launch(void* const* d_in, const int* in_sizes, int n_in,
                              void* d_out, int out_size)
{
    const float* x      = (const float*)d_in[0];   // [B,S,DIN]
    const float* w_qkv  = (const float*)d_in[1];   // [3D, DIN]
    const float* b_qkv  = (const float*)d_in[2];   // [3D]
    const float* w_o    = (const float*)d_in[3];   // [D, D]
    const float* b_o    = (const float*)d_in[4];   // [D]
    float* out = (float*)d_out;                    // [B,S,D]

    float* qkv_buf;
    float* vals_buf;
    cudaGetSymbolAddress((void**)&qkv_buf, g_qkv);
    cudaGetSymbolAddress((void**)&vals_buf, g_vals);

    // Allow >48KB dynamic shared memory for attention
    cudaFuncSetAttribute(attn_kernel,
                         cudaFuncAttributeMaxDynamicSharedMemorySize,
                         ATT_SMEM_BYTES);

    // 1) QKV projection: [4096,1024] @ [3072,1024]^T -> g_qkv [4096,3072]
    {
        dim3 grid(QKV_N / 128, M_ROWS / 128);
        sgemm_kernel<<<grid, 256>>>(x, w_qkv, b_qkv, qkv_buf,
                                    M_ROWS, QKV_N, DIN);
    }

    // 2) Attention -> g_vals [4096,1024]
    {
        dim3 grid(SS / 128, HH, BB);
        attn_kernel<<<grid, 128, ATT_SMEM_BYTES>>>(qkv_buf, vals_buf);
    }

    // 3) Output projection: [4096,1024] @ [1024,1024]^T -> out [4096,1024]
    {
        dim3 grid(DD / 128, M_ROWS / 128);
        sgemm_kernel<<<grid, 256>>>(vals_buf, w_o, b_o, out,
                                    M_ROWS, DD, DIN);
    }
}

// round 3
// speedup vs baseline: 1.4150x; 1.4150x over previous
#include <cuda_runtime.h>
#include <cuda_bf16.h>
#include <cstdint>
#include <math.h>

// Problem constants
#define BB   2
#define SS   2048
#define DIN  1024
#define DD   1024
#define HH   16
#define HDIM 64
#define M_ROWS (BB * SS)      // 4096
#define QKV_N  (3 * DD)       // 3072

// Scratch
__device__ float g_qkv [M_ROWS * QKV_N];
__device__ float g_vals[M_ROWS * DD];

// ---------------------------------------------------------------------------
// Helpers
// ---------------------------------------------------------------------------
__device__ __forceinline__ uint32_t smem_u32(const void* p) {
    uint32_t a;
    asm("{ .reg .u64 t; cvta.to.shared.u64 t, %1; cvt.u32.u64 %0, t; }"
        : "=r"(a) : "l"(p));
    return a;
}

__device__ __forceinline__ uint32_t f2tf32(float f) {
    uint32_t u;
    asm("cvt.rna.tf32.f32 %0, %1;" : "=r"(u) : "f"(f));
    return u;
}

__device__ __forceinline__ void mma_tf32(float* d, const uint32_t* a, const uint32_t* b) {
    asm volatile(
        "mma.sync.aligned.m16n8k8.row.col.f32.tf32.tf32.f32 "
        "{%0,%1,%2,%3}, {%4,%5,%6,%7}, {%8,%9}, {%0,%1,%2,%3};"
        : "+f"(d[0]), "+f"(d[1]), "+f"(d[2]), "+f"(d[3])
        : "r"(a[0]), "r"(a[1]), "r"(a[2]), "r"(a[3]),
          "r"(b[0]), "r"(b[1]));
}

// ---------------------------------------------------------------------------
// mma.sync tf32 GEMM: C[M,N] = A[M,K] @ Bw[N,K]^T + bias[N]
// 128x128 CTA tile, BK=32, 256 threads (8 warps as 2x4), warp tile 64x32.
// Double-buffered cp.async. SMEM row stride 36 floats (16B-aligned, and
// fragment LDS banks = (4*gid+tig)%32 -> conflict-free).
// ---------------------------------------------------------------------------
#define GEMM_BK     32
#define LDS_STR     36
#define TILE_FL     (128 * LDS_STR)              // 4608 floats = 18432 B
#define GEMM_SMEM_BYTES (4 * TILE_FL * 4)        // 2 stages * (A+B) = 73728 B

__global__ __launch_bounds__(256, 2) void gemm_mma_kernel(
    const float* __restrict__ A, const float* __restrict__ Bw,
    const float* __restrict__ bias, float* __restrict__ C,
    int M, int N, int K)
{
    extern __shared__ float smf[];
    const uint32_t sb = smem_u32(smf);
    const int tid  = threadIdx.x;
    const int wid  = tid >> 5;
    const int lane = tid & 31;
    const int gid  = lane >> 2;   // 0..7
    const int tig  = lane & 3;    // 0..3
    const int wm   = (wid >> 2) * 64;  // warp m offset: 0 or 64
    const int wn   = (wid & 3) * 32;   // warp n offset: 0,32,64,96
    const int m0 = blockIdx.y * 128;
    const int n0 = blockIdx.x * 128;

    float acc[4][4][4];
#pragma unroll
    for (int i = 0; i < 4; i++)
#pragma unroll
        for (int j = 0; j < 4; j++)
#pragma unroll
            for (int r = 0; r < 4; r++) acc[i][j][r] = 0.f;

    const int KCH = K / GEMM_BK;

    // --- async load of one 128x32 A tile + 128x32 B tile into stage buffers
    auto load_stage = [&](int chunk) {
        const int stage = chunk & 1;
        const int k0 = chunk * GEMM_BK;
        const uint32_t a_s = sb + stage * (TILE_FL * 4);
        const uint32_t b_s = sb + 2 * (TILE_FL * 4) + stage * (TILE_FL * 4);
        const float* ag = A + (size_t)m0 * K + k0;
        const float* bg = Bw + (size_t)n0 * K + k0;
#pragma unroll
        for (int it = 0; it < 4; it++) {
            int idx = it * 256 + tid;         // 0..1023
            int row = idx >> 3;               // 0..127
            int c4  = (idx & 7) * 4;          // 0,4,...,28
            uint32_t doff = (uint32_t)(row * LDS_STR + c4) * 4;
            asm volatile("cp.async.cg.shared.global [%0], [%1], 16;"
                         :: "r"(a_s + doff), "l"(ag + (size_t)row * K + c4));
            asm volatile("cp.async.cg.shared.global [%0], [%1], 16;"
                         :: "r"(b_s + doff), "l"(bg + (size_t)row * K + c4));
        }
    };

    load_stage(0);
    asm volatile("cp.async.commit_group;" ::: "memory");

    for (int j = 0; j < KCH; j++) {
        if (j + 1 < KCH) {
            load_stage(j + 1);
            asm volatile("cp.async.commit_group;" ::: "memory");
            asm volatile("cp.async.wait_group 1;" ::: "memory");
        } else {
            asm volatile("cp.async.wait_group 0;" ::: "memory");
        }
        __syncthreads();

        const int stage = j & 1;
        const float* as = smf + stage * TILE_FL;
        const float* bs = smf + 2 * TILE_FL + stage * TILE_FL;

#pragma unroll
        for (int kk = 0; kk < 4; kk++) {      // four k8 steps in BK=32
            const int kb = kk * 8 + tig;
            uint32_t afr[4][4];
#pragma unroll
            for (int mt = 0; mt < 4; mt++) {
                const int r = wm + mt * 16 + gid;
                afr[mt][0] = f2tf32(as[r * LDS_STR + kb]);
                afr[mt][1] = f2tf32(as[(r + 8) * LDS_STR + kb]);
                afr[mt][2] = f2tf32(as[r * LDS_STR + kb + 4]);
                afr[mt][3] = f2tf32(as[(r + 8) * LDS_STR + kb + 4]);
            }
            uint32_t bfr[4][2];
#pragma unroll
            for (int nt = 0; nt < 4; nt++) {
                const int c = wn + nt * 8 + gid;
                bfr[nt][0] = f2tf32(bs[c * LDS_STR + kb]);
                bfr[nt][1] = f2tf32(bs[c * LDS_STR + kb + 4]);
            }
#pragma unroll
            for (int mt = 0; mt < 4; mt++)
#pragma unroll
                for (int nt = 0; nt < 4; nt++)
                    mma_tf32(acc[mt][nt], afr[mt], bfr[nt]);
        }
        __syncthreads();
    }

    // Epilogue: bias + store (float2: c0/c1 and c2/c3 are adjacent columns)
#pragma unroll
    for (int mt = 0; mt < 4; mt++) {
        const int row = m0 + wm + mt * 16 + gid;
#pragma unroll
        for (int nt = 0; nt < 4; nt++) {
            const int col = n0 + wn + nt * 8 + tig * 2;
            float2 bv = *(const float2*)(bias + col);
            float2 o0, o1;
            o0.x = acc[mt][nt][0] + bv.x;
            o0.y = acc[mt][nt][1] + bv.y;
            o1.x = acc[mt][nt][2] + bv.x;
            o1.y = acc[mt][nt][3] + bv.y;
            *(float2*)(C + (size_t)row * N + col) = o0;
            *(float2*)(C + (size_t)(row + 8) * N + col) = o1;
        }
    }
}

// ---------------------------------------------------------------------------
// Flash attention, fp32 SIMT (unchanged; known-good from round 1).
// ---------------------------------------------------------------------------
#define ATT_SMEM_FLOATS (4096 + 4096 + 128 * 65)
#define ATT_SMEM_BYTES  (ATT_SMEM_FLOATS * 4)

__global__ __launch_bounds__(128) void attn_kernel(
    const float* __restrict__ qkv, float* __restrict__ vals)
{
    extern __shared__ float fsm[];
    float* k_s = fsm;
    float* v_s = fsm + 4096;
    float* p_s = fsm + 8192;

    const int tid = threadIdx.x;
    const int b = blockIdx.z;
    const int h = blockIdx.y;
    const int q0 = blockIdx.x * 128;
    const float scale = 0.125f;

    const float* qptr = qkv + (size_t)(b * SS + q0 + tid) * QKV_N + h * 192;
    float q[64];
#pragma unroll
    for (int d = 0; d < 64; d += 4)
        *(float4*)&q[d] = *(const float4*)(qptr + d);

    float m_i = -1e30f, l_i = 0.f;
    float acc[64];
#pragma unroll
    for (int d = 0; d < 64; d++) acc[d] = 0.f;

    const float* kbase = qkv + (size_t)(b * SS) * QKV_N + h * 192 + 64;
    float* prow = p_s + tid * 65;

    for (int kt = 0; kt < SS / 64; kt++) {
        const float* kt_ptr = kbase + (size_t)kt * 64 * QKV_N;
#pragma unroll
        for (int i = tid; i < 64 * 16; i += 128) {
            int r = i >> 4;
            int c = (i & 15) << 2;
            *(float4*)&k_s[r * 64 + c] = *(const float4*)(kt_ptr + (size_t)r * QKV_N + c);
            *(float4*)&v_s[r * 64 + c] = *(const float4*)(kt_ptr + (size_t)r * QKV_N + 64 + c);
        }
        __syncthreads();

        float tmax = -1e30f;
#pragma unroll 4
        for (int j = 0; j < 64; j++) {
            const float* kr = k_s + j * 64;
            float s = 0.f;
#pragma unroll
            for (int d = 0; d < 64; d += 4) {
                float4 kv = *(const float4*)(kr + d);
                s += q[d] * kv.x + q[d + 1] * kv.y + q[d + 2] * kv.z + q[d + 3] * kv.w;
            }
            s *= scale;
            prow[j] = s;
            tmax = fmaxf(tmax, s);
        }

        float m_new = fmaxf(m_i, tmax);
        float corr = __expf(m_i - m_new);
        l_i *= corr;
#pragma unroll
        for (int d = 0; d < 64; d++) acc[d] *= corr;
        m_i = m_new;

#pragma unroll 2
        for (int j = 0; j < 64; j++) {
            float p = __expf(prow[j] - m_new);
            l_i += p;
            const float* vr = v_s + j * 64;
#pragma unroll
            for (int d = 0; d < 64; d += 4) {
                float4 vv = *(const float4*)(vr + d);
                acc[d]     += p * vv.x;
                acc[d + 1] += p * vv.y;
                acc[d + 2] += p * vv.z;
                acc[d + 3] += p * vv.w;
            }
        }
        __syncthreads();
    }

    const float inv = 1.f / l_i;
    float* optr = vals + (size_t)(b * SS + q0 + tid) * DD + h * HDIM;
#pragma unroll
    for (int d = 0; d < 64; d += 4) {
        float4 o;
        o.x = acc[d] * inv;
        o.y = acc[d + 1] * inv;
        o.z = acc[d + 2] * inv;
        o.w = acc[d + 3] * inv;
        *(float4*)(optr + d) = o;
    }
}

// ---------------------------------------------------------------------------
// Launch
// ---------------------------------------------------------------------------
extern "C" void kernel_launch(void* const* d_in, const int* in_sizes, int n_in,
                              void* d_out, int out_size)
{
    const float* x      = (const float*)d_in[0];
    const float* w_qkv  = (const float*)d_in[1];
    const float* b_qkv  = (const float*)d_in[2];
    const float* w_o    = (const float*)d_in[3];
    const float* b_o    = (const float*)d_in[4];
    float* out = (float*)d_out;

    float* qkv_buf;
    float* vals_buf;
    cudaGetSymbolAddress((void**)&qkv_buf, g_qkv);
    cudaGetSymbolAddress((void**)&vals_buf, g_vals);

    cudaFuncSetAttribute(gemm_mma_kernel,
                         cudaFuncAttributeMaxDynamicSharedMemorySize,
                         GEMM_SMEM_BYTES);
    cudaFuncSetAttribute(attn_kernel,
                         cudaFuncAttributeMaxDynamicSharedMemorySize,
                         ATT_SMEM_BYTES);

    // 1) QKV projection -> g_qkv [4096, 3072]
    {
        dim3 grid(QKV_N / 128, M_ROWS / 128);
        gemm_mma_kernel<<<grid, 256, GEMM_SMEM_BYTES>>>(
            x, w_qkv, b_qkv, qkv_buf, M_ROWS, QKV_N, DIN);
    }

    // 2) Attention -> g_vals [4096, 1024]
    {
        dim3 grid(SS / 128, HH, BB);
        attn_kernel<<<grid, 128, ATT_SMEM_BYTES>>>(qkv_buf, vals_buf);
    }

    // 3) Output projection -> out [4096, 1024]
    {
        dim3 grid(DD / 128, M_ROWS / 128);
        gemm_mma_kernel<<<grid, 256, GEMM_SMEM_BYTES>>>(
            vals_buf, w_o, b_o, out, M_ROWS, DD, DIN);
    }
}

// round 4
// speedup vs baseline: 3.9738x; 2.8084x over previous
#include <cuda_runtime.h>
#include <cuda_bf16.h>
#include <cstdint>
#include <math.h>

// Problem constants
#define BB   2
#define SS   2048
#define DIN  1024
#define DD   1024
#define HH   16
#define HDIM 64
#define M_ROWS (BB * SS)      // 4096
#define QKV_N  (3 * DD)       // 3072

// Scratch
__device__ float g_qkv [M_ROWS * QKV_N];
__device__ float g_vals[M_ROWS * DD];

// ---------------------------------------------------------------------------
// Helpers
// ---------------------------------------------------------------------------
__device__ __forceinline__ uint32_t smem_u32(const void* p) {
    uint32_t a;
    asm("{ .reg .u64 t; cvta.to.shared.u64 t, %1; cvt.u32.u64 %0, t; }"
        : "=r"(a) : "l"(p));
    return a;
}

__device__ __forceinline__ uint32_t f2tf32(float f) {
    uint32_t u;
    asm("cvt.rna.tf32.f32 %0, %1;" : "=r"(u) : "f"(f));
    return u;
}

__device__ __forceinline__ float ex2(float x) {
    float r;
    asm("ex2.approx.f32 %0, %1;" : "=f"(r) : "f"(x));
    return r;
}

__device__ __forceinline__ void mma_tf32(float* d, const uint32_t* a, const uint32_t* b) {
    asm volatile(
        "mma.sync.aligned.m16n8k8.row.col.f32.tf32.tf32.f32 "
        "{%0,%1,%2,%3}, {%4,%5,%6,%7}, {%8,%9}, {%0,%1,%2,%3};"
        : "+f"(d[0]), "+f"(d[1]), "+f"(d[2]), "+f"(d[3])
        : "r"(a[0]), "r"(a[1]), "r"(a[2]), "r"(a[3]),
          "r"(b[0]), "r"(b[1]));
}

// ---------------------------------------------------------------------------
// mma.sync tf32 GEMM (unchanged from round 3): C = A @ Bw^T + bias
// ---------------------------------------------------------------------------
#define GEMM_BK     32
#define LDS_STR     36
#define TILE_FL     (128 * LDS_STR)
#define GEMM_SMEM_BYTES (4 * TILE_FL * 4)

__global__ __launch_bounds__(256, 2) void gemm_mma_kernel(
    const float* __restrict__ A, const float* __restrict__ Bw,
    const float* __restrict__ bias, float* __restrict__ C,
    int M, int N, int K)
{
    extern __shared__ float smf[];
    const uint32_t sb = smem_u32(smf);
    const int tid  = threadIdx.x;
    const int wid  = tid >> 5;
    const int lane = tid & 31;
    const int gid  = lane >> 2;
    const int tig  = lane & 3;
    const int wm   = (wid >> 2) * 64;
    const int wn   = (wid & 3) * 32;
    const int m0 = blockIdx.y * 128;
    const int n0 = blockIdx.x * 128;

    float acc[4][4][4];
#pragma unroll
    for (int i = 0; i < 4; i++)
#pragma unroll
        for (int j = 0; j < 4; j++)
#pragma unroll
            for (int r = 0; r < 4; r++) acc[i][j][r] = 0.f;

    const int KCH = K / GEMM_BK;

    auto load_stage = [&](int chunk) {
        const int stage = chunk & 1;
        const int k0 = chunk * GEMM_BK;
        const uint32_t a_s = sb + stage * (TILE_FL * 4);
        const uint32_t b_s = sb + 2 * (TILE_FL * 4) + stage * (TILE_FL * 4);
        const float* ag = A + (size_t)m0 * K + k0;
        const float* bg = Bw + (size_t)n0 * K + k0;
#pragma unroll
        for (int it = 0; it < 4; it++) {
            int idx = it * 256 + tid;
            int row = idx >> 3;
            int c4  = (idx & 7) * 4;
            uint32_t doff = (uint32_t)(row * LDS_STR + c4) * 4;
            asm volatile("cp.async.cg.shared.global [%0], [%1], 16;"
                         :: "r"(a_s + doff), "l"(ag + (size_t)row * K + c4));
            asm volatile("cp.async.cg.shared.global [%0], [%1], 16;"
                         :: "r"(b_s + doff), "l"(bg + (size_t)row * K + c4));
        }
    };

    load_stage(0);
    asm volatile("cp.async.commit_group;" ::: "memory");

    for (int j = 0; j < KCH; j++) {
        if (j + 1 < KCH) {
            load_stage(j + 1);
            asm volatile("cp.async.commit_group;" ::: "memory");
            asm volatile("cp.async.wait_group 1;" ::: "memory");
        } else {
            asm volatile("cp.async.wait_group 0;" ::: "memory");
        }
        __syncthreads();

        const int stage = j & 1;
        const float* as = smf + stage * TILE_FL;
        const float* bs = smf + 2 * TILE_FL + stage * TILE_FL;

#pragma unroll
        for (int kk = 0; kk < 4; kk++) {
            const int kb = kk * 8 + tig;
            uint32_t afr[4][4];
#pragma unroll
            for (int mt = 0; mt < 4; mt++) {
                const int r = wm + mt * 16 + gid;
                afr[mt][0] = f2tf32(as[r * LDS_STR + kb]);
                afr[mt][1] = f2tf32(as[(r + 8) * LDS_STR + kb]);
                afr[mt][2] = f2tf32(as[r * LDS_STR + kb + 4]);
                afr[mt][3] = f2tf32(as[(r + 8) * LDS_STR + kb + 4]);
            }
            uint32_t bfr[4][2];
#pragma unroll
            for (int nt = 0; nt < 4; nt++) {
                const int c = wn + nt * 8 + gid;
                bfr[nt][0] = f2tf32(bs[c * LDS_STR + kb]);
                bfr[nt][1] = f2tf32(bs[c * LDS_STR + kb + 4]);
            }
#pragma unroll
            for (int mt = 0; mt < 4; mt++)
#pragma unroll
                for (int nt = 0; nt < 4; nt++)
                    mma_tf32(acc[mt][nt], afr[mt], bfr[nt]);
        }
        __syncthreads();
    }

#pragma unroll
    for (int mt = 0; mt < 4; mt++) {
        const int row = m0 + wm + mt * 16 + gid;
#pragma unroll
        for (int nt = 0; nt < 4; nt++) {
            const int col = n0 + wn + nt * 8 + tig * 2;
            float2 bv = *(const float2*)(bias + col);
            float2 o0, o1;
            o0.x = acc[mt][nt][0] + bv.x;
            o0.y = acc[mt][nt][1] + bv.y;
            o1.x = acc[mt][nt][2] + bv.x;
            o1.y = acc[mt][nt][3] + bv.y;
            *(float2*)(C + (size_t)row * N + col) = o0;
            *(float2*)(C + (size_t)(row + 8) * N + col) = o1;
        }
    }
}

// ---------------------------------------------------------------------------
// Flash attention with mma.sync tf32.
// Block: 256 thr / 8 warps; 128 q-rows per block (16 per warp).
// Key tiles of 64, double-buffered cp.async.
// SMEM strides chosen for conflict-free fragment LDS:
//   k_s, p_s stride 68 (68%32=4 -> bank 4*gid+tig), v_s stride 72 (8*tig+gid).
// ---------------------------------------------------------------------------
#define AT_KSTR 68
#define AT_VSTR 72
#define AT_PSTR 68
#define AT_KFL  (64 * AT_KSTR)          // 4352 floats per stage
#define AT_VFL  (64 * AT_VSTR)          // 4608
#define AT_V0   (2 * AT_KFL)            // after 2 K stages
#define AT_P0   (AT_V0 + 2 * AT_VFL)    // after 2 V stages
#define ATT_SMEM_FLOATS (AT_P0 + 128 * AT_PSTR)
#define ATT_SMEM_BYTES  (ATT_SMEM_FLOATS * 4)   // 106496

__global__ __launch_bounds__(256) void attn_mma_kernel(
    const float* __restrict__ qkv, float* __restrict__ vals)
{
    extern __shared__ float fsm[];
    const uint32_t sb = smem_u32(fsm);
    float* k_sm = fsm;
    float* v_sm = fsm + AT_V0;
    uint32_t* p_sm = (uint32_t*)(fsm + AT_P0);

    const int tid  = threadIdx.x;
    const int wid  = tid >> 5;
    const int lane = tid & 31;
    const int gid  = lane >> 2;   // 0..7
    const int tig  = lane & 3;    // 0..3
    const int b  = blockIdx.z;
    const int h  = blockIdx.y;
    const int q0 = blockIdx.x * 128;

    // Fold softmax scale and log2(e) into Q: S' = S * log2(e) so p = 2^(s'-m')
    const float qscale = 0.125f * 1.4426950408889634f;

    // --- Preload Q fragments (held for whole kernel) -------------------------
    // Warp owns q rows [q0 + wid*16, +16). A-frag for k-step kk:
    //   a0=(gid, 8kk+tig) a1=(gid+8, ..) a2=(gid, 8kk+tig+4) a3=(gid+8, ..+4)
    uint32_t qf[8][4];
    {
        const float* qlo = qkv + (size_t)(b * SS + q0 + wid * 16 + gid) * QKV_N + h * 192;
        const float* qhi = qlo + 8 * QKV_N;
#pragma unroll
        for (int kk = 0; kk < 8; kk++) {
            const int c = kk * 8 + tig;
            qf[kk][0] = f2tf32(qlo[c] * qscale);
            qf[kk][1] = f2tf32(qhi[c] * qscale);
            qf[kk][2] = f2tf32(qlo[c + 4] * qscale);
            qf[kk][3] = f2tf32(qhi[c + 4] * qscale);
        }
    }

    // K/V tile async loader: tile kt -> stage kt&1
    const float* kvbase = qkv + (size_t)(b * SS) * QKV_N + h * 192 + 64;
    auto load_tile = [&](int kt) {
        const int stage = kt & 1;
        const float* src = kvbase + (size_t)kt * 64 * QKV_N;
        const uint32_t kdst = sb + (stage * AT_KFL) * 4;
        const uint32_t vdst = sb + (AT_V0 + stage * AT_VFL) * 4;
#pragma unroll
        for (int it = 0; it < 4; it++) {
            int idx = it * 256 + tid;          // 0..1023
            int row = idx >> 4;                // 0..63
            int c4  = (idx & 15) * 4;          // 0..60
            const float* g = src + (size_t)row * QKV_N + c4;
            asm volatile("cp.async.cg.shared.global [%0], [%1], 16;"
                         :: "r"(kdst + (uint32_t)(row * AT_KSTR + c4) * 4), "l"(g));
            asm volatile("cp.async.cg.shared.global [%0], [%1], 16;"
                         :: "r"(vdst + (uint32_t)(row * AT_VSTR + c4) * 4), "l"(g + 64));
        }
    };

    float m0 = -1e30f, m1 = -1e30f, l0 = 0.f, l1 = 0.f;
    float oacc[8][4];
#pragma unroll
    for (int nt = 0; nt < 8; nt++)
#pragma unroll
        for (int r = 0; r < 4; r++) oacc[nt][r] = 0.f;

    uint32_t* prow = p_sm + (wid * 16) * AT_PSTR;

    load_tile(0);
    asm volatile("cp.async.commit_group;" ::: "memory");

    for (int kt = 0; kt < SS / 64; kt++) {
        if (kt + 1 < SS / 64) {
            load_tile(kt + 1);
            asm volatile("cp.async.commit_group;" ::: "memory");
            asm volatile("cp.async.wait_group 1;" ::: "memory");
        } else {
            asm volatile("cp.async.wait_group 0;" ::: "memory");
        }
        __syncthreads();

        const int stage = kt & 1;
        const float* ks = k_sm + stage * AT_KFL;
        const float* vs = v_sm + stage * AT_VFL;

        // ---- S = Q @ K^T  (16 x 64 per warp) ----
        float sacc[8][4];
#pragma unroll
        for (int nt = 0; nt < 8; nt++)
#pragma unroll
            for (int r = 0; r < 4; r++) sacc[nt][r] = 0.f;

#pragma unroll
        for (int kk = 0; kk < 8; kk++) {
            const int kb = kk * 8 + tig;
            uint32_t bfr[8][2];
#pragma unroll
            for (int nt = 0; nt < 8; nt++) {
                const int key = nt * 8 + gid;
                bfr[nt][0] = f2tf32(ks[key * AT_KSTR + kb]);
                bfr[nt][1] = f2tf32(ks[key * AT_KSTR + kb + 4]);
            }
#pragma unroll
            for (int nt = 0; nt < 8; nt++)
                mma_tf32(sacc[nt], qf[kk], bfr[nt]);
        }

        // ---- online softmax (log2 domain) ----
        float tmax0 = -1e30f, tmax1 = -1e30f;
#pragma unroll
        for (int nt = 0; nt < 8; nt++) {
            tmax0 = fmaxf(tmax0, fmaxf(sacc[nt][0], sacc[nt][1]));
            tmax1 = fmaxf(tmax1, fmaxf(sacc[nt][2], sacc[nt][3]));
        }
        tmax0 = fmaxf(tmax0, __shfl_xor_sync(0xffffffffu, tmax0, 1));
        tmax0 = fmaxf(tmax0, __shfl_xor_sync(0xffffffffu, tmax0, 2));
        tmax1 = fmaxf(tmax1, __shfl_xor_sync(0xffffffffu, tmax1, 1));
        tmax1 = fmaxf(tmax1, __shfl_xor_sync(0xffffffffu, tmax1, 2));

        const float mn0 = fmaxf(m0, tmax0);
        const float mn1 = fmaxf(m1, tmax1);
        const float corr0 = ex2(m0 - mn0);
        const float corr1 = ex2(m1 - mn1);
        m0 = mn0; m1 = mn1;

        float sum0 = 0.f, sum1 = 0.f;
#pragma unroll
        for (int nt = 0; nt < 8; nt++) {
            float p0 = ex2(sacc[nt][0] - mn0);
            float p1 = ex2(sacc[nt][1] - mn0);
            float p2 = ex2(sacc[nt][2] - mn1);
            float p3 = ex2(sacc[nt][3] - mn1);
            sum0 += p0 + p1;
            sum1 += p2 + p3;
            const int c = nt * 8 + 2 * tig;
            prow[(gid) * AT_PSTR + c]     = f2tf32(p0);
            prow[(gid) * AT_PSTR + c + 1] = f2tf32(p1);
            prow[(gid + 8) * AT_PSTR + c]     = f2tf32(p2);
            prow[(gid + 8) * AT_PSTR + c + 1] = f2tf32(p3);
            // rescale O accumulator
            oacc[nt][0] *= corr0;
            oacc[nt][1] *= corr0;
            oacc[nt][2] *= corr1;
            oacc[nt][3] *= corr1;
        }
        sum0 += __shfl_xor_sync(0xffffffffu, sum0, 1);
        sum0 += __shfl_xor_sync(0xffffffffu, sum0, 2);
        sum1 += __shfl_xor_sync(0xffffffffu, sum1, 1);
        sum1 += __shfl_xor_sync(0xffffffffu, sum1, 2);
        l0 = l0 * corr0 + sum0;
        l1 = l1 * corr1 + sum1;

        __syncwarp();

        // ---- O += P @ V  (16 x 64 per warp, k = 64 keys) ----
#pragma unroll
        for (int kk = 0; kk < 8; kk++) {
            uint32_t afr[4];
            afr[0] = prow[gid * AT_PSTR + kk * 8 + tig];
            afr[1] = prow[(gid + 8) * AT_PSTR + kk * 8 + tig];
            afr[2] = prow[gid * AT_PSTR + kk * 8 + tig + 4];
            afr[3] = prow[(gid + 8) * AT_PSTR + kk * 8 + tig + 4];
            uint32_t bfr[8][2];
#pragma unroll
            for (int nt = 0; nt < 8; nt++) {
                const int d = nt * 8 + gid;
                bfr[nt][0] = f2tf32(vs[(kk * 8 + tig) * AT_VSTR + d]);
                bfr[nt][1] = f2tf32(vs[(kk * 8 + tig + 4) * AT_VSTR + d]);
            }
#pragma unroll
            for (int nt = 0; nt < 8; nt++)
                mma_tf32(oacc[nt], afr, bfr[nt]);
        }
        __syncthreads();   // compute done before next-next tile overwrites stage
    }

    // ---- normalize and write out ----
    const float inv0 = 1.f / l0;
    const float inv1 = 1.f / l1;
    float* olo = vals + (size_t)(b * SS + q0 + wid * 16 + gid) * DD + h * HDIM;
    float* ohi = olo + 8 * DD;
#pragma unroll
    for (int nt = 0; nt < 8; nt++) {
        const int c = nt * 8 + 2 * tig;
        float2 r0, r1;
        r0.x = oacc[nt][0] * inv0;
        r0.y = oacc[nt][1] * inv0;
        r1.x = oacc[nt][2] * inv1;
        r1.y = oacc[nt][3] * inv1;
        *(float2*)(olo + c) = r0;
        *(float2*)(ohi + c) = r1;
    }
}

// ---------------------------------------------------------------------------
// Launch
// ---------------------------------------------------------------------------
extern "C" void kernel_launch(void* const* d_in, const int* in_sizes, int n_in,
                              void* d_out, int out_size)
{
    const float* x      = (const float*)d_in[0];
    const float* w_qkv  = (const float*)d_in[1];
    const float* b_qkv  = (const float*)d_in[2];
    const float* w_o    = (const float*)d_in[3];
    const float* b_o    = (const float*)d_in[4];
    float* out = (float*)d_out;

    float* qkv_buf;
    float* vals_buf;
    cudaGetSymbolAddress((void**)&qkv_buf, g_qkv);
    cudaGetSymbolAddress((void**)&vals_buf, g_vals);

    cudaFuncSetAttribute(gemm_mma_kernel,
                         cudaFuncAttributeMaxDynamicSharedMemorySize,
                         GEMM_SMEM_BYTES);
    cudaFuncSetAttribute(attn_mma_kernel,
                         cudaFuncAttributeMaxDynamicSharedMemorySize,
                         ATT_SMEM_BYTES);

    // 1) QKV projection -> g_qkv [4096, 3072]
    {
        dim3 grid(QKV_N / 128, M_ROWS / 128);
        gemm_mma_kernel<<<grid, 256, GEMM_SMEM_BYTES>>>(
            x, w_qkv, b_qkv, qkv_buf, M_ROWS, QKV_N, DIN);
    }

    // 2) Attention -> g_vals [4096, 1024]
    {
        dim3 grid(SS / 128, HH, BB);
        attn_mma_kernel<<<grid, 256, ATT_SMEM_BYTES>>>(qkv_buf, vals_buf);
    }

    // 3) Output projection -> out [4096, 1024]
    {
        dim3 grid(DD / 128, M_ROWS / 128);
        gemm_mma_kernel<<<grid, 256, GEMM_SMEM_BYTES>>>(
            vals_buf, w_o, b_o, out, M_ROWS, DD, DIN);
    }
}

// round 5
// speedup vs baseline: 4.2638x; 1.0730x over previous
#include <cuda_runtime.h>
#include <cuda_bf16.h>
#include <cstdint>
#include <math.h>

// Problem constants
#define BB   2
#define SS   2048
#define DIN  1024
#define DD   1024
#define HH   16
#define HDIM 64
#define M_ROWS (BB * SS)      // 4096
#define QKV_N  (3 * DD)       // 3072

// Scratch (tf32-bit-pattern fp32 buffers)
__device__ float g_qkv [M_ROWS * QKV_N];   // qkv, tf32-rounded, [H][3*HD] packing
__device__ float g_vals[M_ROWS * DD];      // attention out, tf32-rounded
__device__ float g_xc  [M_ROWS * DIN];     // x, tf32-rounded
__device__ float g_wqc [QKV_N * DIN];      // w_qkv, tf32-rounded
__device__ float g_woc [DD * DD];          // w_o, tf32-rounded

// ---------------------------------------------------------------------------
// Helpers
// ---------------------------------------------------------------------------
__device__ __forceinline__ uint32_t smem_u32(const void* p) {
    uint32_t a;
    asm("{ .reg .u64 t; cvta.to.shared.u64 t, %1; cvt.u32.u64 %0, t; }"
        : "=r"(a) : "l"(p));
    return a;
}

__device__ __forceinline__ uint32_t f2tf32(float f) {
    uint32_t u;
    asm("cvt.rna.tf32.f32 %0, %1;" : "=r"(u) : "f"(f));
    return u;
}

__device__ __forceinline__ float ex2(float x) {
    float r;
    asm("ex2.approx.f32 %0, %1;" : "=f"(r) : "f"(x));
    return r;
}

__device__ __forceinline__ void mma_tf32(float* d, const uint32_t* a, const uint32_t* b) {
    asm volatile(
        "mma.sync.aligned.m16n8k8.row.col.f32.tf32.tf32.f32 "
        "{%0,%1,%2,%3}, {%4,%5,%6,%7}, {%8,%9}, {%0,%1,%2,%3};"
        : "+f"(d[0]), "+f"(d[1]), "+f"(d[2]), "+f"(d[3])
        : "r"(a[0]), "r"(a[1]), "r"(a[2]), "r"(a[3]),
          "r"(b[0]), "r"(b[1]));
}

// ---------------------------------------------------------------------------
// Elementwise tf32 pre-conversion (vectorized)
// ---------------------------------------------------------------------------
__global__ __launch_bounds__(256) void tf32_cvt_kernel(
    const float4* __restrict__ s, float4* __restrict__ d, int n4)
{
    int i = blockIdx.x * blockDim.x + threadIdx.x;
    if (i < n4) {
        float4 v = s[i];
        uint4 o;
        o.x = f2tf32(v.x);
        o.y = f2tf32(v.y);
        o.z = f2tf32(v.z);
        o.w = f2tf32(v.w);
        ((uint4*)d)[i] = o;
    }
}

// ---------------------------------------------------------------------------
// mma.sync tf32 GEMM, operands pre-converted (no cvt in mainloop):
// C = A @ Bw^T + bias.  If cvt_out != 0, output is tf32-rounded.
// 128x128 CTA, BK=32, 256 thr (8 warps 2x4), warp tile 64x32, dbl-buffered.
// ---------------------------------------------------------------------------
#define GEMM_BK     32
#define LDS_STR     36
#define TILE_FL     (128 * LDS_STR)
#define GEMM_SMEM_BYTES (4 * TILE_FL * 4)

__global__ __launch_bounds__(256, 2) void gemm_mma_kernel(
    const float* __restrict__ A, const float* __restrict__ Bw,
    const float* __restrict__ bias, float* __restrict__ C,
    int M, int N, int K, int cvt_out)
{
    extern __shared__ float smf[];
    const uint32_t sb = smem_u32(smf);
    const int tid  = threadIdx.x;
    const int wid  = tid >> 5;
    const int lane = tid & 31;
    const int gid  = lane >> 2;
    const int tig  = lane & 3;
    const int wm   = (wid >> 2) * 64;
    const int wn   = (wid & 3) * 32;
    const int m0 = blockIdx.y * 128;
    const int n0 = blockIdx.x * 128;

    float acc[4][4][4];
#pragma unroll
    for (int i = 0; i < 4; i++)
#pragma unroll
        for (int j = 0; j < 4; j++)
#pragma unroll
            for (int r = 0; r < 4; r++) acc[i][j][r] = 0.f;

    const int KCH = K / GEMM_BK;

    auto load_stage = [&](int chunk) {
        const int stage = chunk & 1;
        const int k0 = chunk * GEMM_BK;
        const uint32_t a_s = sb + stage * (TILE_FL * 4);
        const uint32_t b_s = sb + 2 * (TILE_FL * 4) + stage * (TILE_FL * 4);
        const float* ag = A + (size_t)m0 * K + k0;
        const float* bg = Bw + (size_t)n0 * K + k0;
#pragma unroll
        for (int it = 0; it < 4; it++) {
            int idx = it * 256 + tid;
            int row = idx >> 3;
            int c4  = (idx & 7) * 4;
            uint32_t doff = (uint32_t)(row * LDS_STR + c4) * 4;
            asm volatile("cp.async.cg.shared.global [%0], [%1], 16;"
                         :: "r"(a_s + doff), "l"(ag + (size_t)row * K + c4));
            asm volatile("cp.async.cg.shared.global [%0], [%1], 16;"
                         :: "r"(b_s + doff), "l"(bg + (size_t)row * K + c4));
        }
    };

    load_stage(0);
    asm volatile("cp.async.commit_group;" ::: "memory");

    for (int j = 0; j < KCH; j++) {
        if (j + 1 < KCH) {
            load_stage(j + 1);
            asm volatile("cp.async.commit_group;" ::: "memory");
            asm volatile("cp.async.wait_group 1;" ::: "memory");
        } else {
            asm volatile("cp.async.wait_group 0;" ::: "memory");
        }
        __syncthreads();

        const int stage = j & 1;
        const uint32_t* as = (const uint32_t*)(smf + stage * TILE_FL);
        const uint32_t* bs = (const uint32_t*)(smf + 2 * TILE_FL + stage * TILE_FL);

#pragma unroll
        for (int kk = 0; kk < 4; kk++) {
            const int kb = kk * 8 + tig;
            uint32_t afr[4][4];
#pragma unroll
            for (int mt = 0; mt < 4; mt++) {
                const int r = wm + mt * 16 + gid;
                afr[mt][0] = as[r * LDS_STR + kb];
                afr[mt][1] = as[(r + 8) * LDS_STR + kb];
                afr[mt][2] = as[r * LDS_STR + kb + 4];
                afr[mt][3] = as[(r + 8) * LDS_STR + kb + 4];
            }
            uint32_t bfr[4][2];
#pragma unroll
            for (int nt = 0; nt < 4; nt++) {
                const int c = wn + nt * 8 + gid;
                bfr[nt][0] = bs[c * LDS_STR + kb];
                bfr[nt][1] = bs[c * LDS_STR + kb + 4];
            }
#pragma unroll
            for (int mt = 0; mt < 4; mt++)
#pragma unroll
                for (int nt = 0; nt < 4; nt++)
                    mma_tf32(acc[mt][nt], afr[mt], bfr[nt]);
        }
        __syncthreads();
    }

#pragma unroll
    for (int mt = 0; mt < 4; mt++) {
        const int row = m0 + wm + mt * 16 + gid;
#pragma unroll
        for (int nt = 0; nt < 4; nt++) {
            const int col = n0 + wn + nt * 8 + tig * 2;
            float2 bv = *(const float2*)(bias + col);
            float2 o0, o1;
            o0.x = acc[mt][nt][0] + bv.x;
            o0.y = acc[mt][nt][1] + bv.y;
            o1.x = acc[mt][nt][2] + bv.x;
            o1.y = acc[mt][nt][3] + bv.y;
            if (cvt_out) {
                o0.x = __uint_as_float(f2tf32(o0.x));
                o0.y = __uint_as_float(f2tf32(o0.y));
                o1.x = __uint_as_float(f2tf32(o1.x));
                o1.y = __uint_as_float(f2tf32(o1.y));
            }
            *(float2*)(C + (size_t)row * N + col) = o0;
            *(float2*)(C + (size_t)(row + 8) * N + col) = o1;
        }
    }
}

// ---------------------------------------------------------------------------
// Flash attention, mma.sync tf32; K/V/Q arrive pre-tf32-rounded (no cvt on
// K/V fragment loads). Output written tf32-rounded for the O-projection.
// Block: 256 thr / 8 warps; 128 q-rows per block; KV tiles of 64, dbl-buffer.
// ---------------------------------------------------------------------------
#define AT_KSTR 68
#define AT_VSTR 72
#define AT_PSTR 68
#define AT_KFL  (64 * AT_KSTR)
#define AT_VFL  (64 * AT_VSTR)
#define AT_V0   (2 * AT_KFL)
#define AT_P0   (AT_V0 + 2 * AT_VFL)
#define ATT_SMEM_FLOATS (AT_P0 + 128 * AT_PSTR)
#define ATT_SMEM_BYTES  (ATT_SMEM_FLOATS * 4)

__global__ __launch_bounds__(256) void attn_mma_kernel(
    const float* __restrict__ qkv, float* __restrict__ vals)
{
    extern __shared__ float fsm[];
    const uint32_t sb = smem_u32(fsm);
    const uint32_t* k_sm = (const uint32_t*)fsm;
    const uint32_t* v_sm = (const uint32_t*)(fsm + AT_V0);
    uint32_t* p_sm = (uint32_t*)(fsm + AT_P0);

    const int tid  = threadIdx.x;
    const int wid  = tid >> 5;
    const int lane = tid & 31;
    const int gid  = lane >> 2;
    const int tig  = lane & 3;
    const int b  = blockIdx.z;
    const int h  = blockIdx.y;
    const int q0 = blockIdx.x * 128;

    const float qscale = 0.125f * 1.4426950408889634f;

    uint32_t qf[8][4];
    {
        const float* qlo = qkv + (size_t)(b * SS + q0 + wid * 16 + gid) * QKV_N + h * 192;
        const float* qhi = qlo + 8 * QKV_N;
#pragma unroll
        for (int kk = 0; kk < 8; kk++) {
            const int c = kk * 8 + tig;
            qf[kk][0] = f2tf32(qlo[c] * qscale);
            qf[kk][1] = f2tf32(qhi[c] * qscale);
            qf[kk][2] = f2tf32(qlo[c + 4] * qscale);
            qf[kk][3] = f2tf32(qhi[c + 4] * qscale);
        }
    }

    const float* kvbase = qkv + (size_t)(b * SS) * QKV_N + h * 192 + 64;
    auto load_tile = [&](int kt) {
        const int stage = kt & 1;
        const float* src = kvbase + (size_t)kt * 64 * QKV_N;
        const uint32_t kdst = sb + (stage * AT_KFL) * 4;
        const uint32_t vdst = sb + (AT_V0 + stage * AT_VFL) * 4;
#pragma unroll
        for (int it = 0; it < 4; it++) {
            int idx = it * 256 + tid;
            int row = idx >> 4;
            int c4  = (idx & 15) * 4;
            const float* g = src + (size_t)row * QKV_N + c4;
            asm volatile("cp.async.cg.shared.global [%0], [%1], 16;"
                         :: "r"(kdst + (uint32_t)(row * AT_KSTR + c4) * 4), "l"(g));
            asm volatile("cp.async.cg.shared.global [%0], [%1], 16;"
                         :: "r"(vdst + (uint32_t)(row * AT_VSTR + c4) * 4), "l"(g + 64));
        }
    };

    float m0 = -1e30f, m1 = -1e30f, l0 = 0.f, l1 = 0.f;
    float oacc[8][4];
#pragma unroll
    for (int nt = 0; nt < 8; nt++)
#pragma unroll
        for (int r = 0; r < 4; r++) oacc[nt][r] = 0.f;

    uint32_t* prow = p_sm + (wid * 16) * AT_PSTR;

    load_tile(0);
    asm volatile("cp.async.commit_group;" ::: "memory");

    for (int kt = 0; kt < SS / 64; kt++) {
        if (kt + 1 < SS / 64) {
            load_tile(kt + 1);
            asm volatile("cp.async.commit_group;" ::: "memory");
            asm volatile("cp.async.wait_group 1;" ::: "memory");
        } else {
            asm volatile("cp.async.wait_group 0;" ::: "memory");
        }
        __syncthreads();

        const int stage = kt & 1;
        const uint32_t* ks = k_sm + stage * AT_KFL;
        const uint32_t* vs = v_sm + stage * AT_VFL;

        // ---- S = Q @ K^T ----
        float sacc[8][4];
#pragma unroll
        for (int nt = 0; nt < 8; nt++)
#pragma unroll
            for (int r = 0; r < 4; r++) sacc[nt][r] = 0.f;

#pragma unroll
        for (int kk = 0; kk < 8; kk++) {
            const int kb = kk * 8 + tig;
            uint32_t bfr[8][2];
#pragma unroll
            for (int nt = 0; nt < 8; nt++) {
                const int key = nt * 8 + gid;
                bfr[nt][0] = ks[key * AT_KSTR + kb];
                bfr[nt][1] = ks[key * AT_KSTR + kb + 4];
            }
#pragma unroll
            for (int nt = 0; nt < 8; nt++)
                mma_tf32(sacc[nt], qf[kk], bfr[nt]);
        }

        // ---- online softmax (log2 domain) ----
        float tmax0 = -1e30f, tmax1 = -1e30f;
#pragma unroll
        for (int nt = 0; nt < 8; nt++) {
            tmax0 = fmaxf(tmax0, fmaxf(sacc[nt][0], sacc[nt][1]));
            tmax1 = fmaxf(tmax1, fmaxf(sacc[nt][2], sacc[nt][3]));
        }
        tmax0 = fmaxf(tmax0, __shfl_xor_sync(0xffffffffu, tmax0, 1));
        tmax0 = fmaxf(tmax0, __shfl_xor_sync(0xffffffffu, tmax0, 2));
        tmax1 = fmaxf(tmax1, __shfl_xor_sync(0xffffffffu, tmax1, 1));
        tmax1 = fmaxf(tmax1, __shfl_xor_sync(0xffffffffu, tmax1, 2));

        const float mn0 = fmaxf(m0, tmax0);
        const float mn1 = fmaxf(m1, tmax1);
        const float corr0 = ex2(m0 - mn0);
        const float corr1 = ex2(m1 - mn1);
        m0 = mn0; m1 = mn1;

        float sum0 = 0.f, sum1 = 0.f;
#pragma unroll
        for (int nt = 0; nt < 8; nt++) {
            float p0 = ex2(sacc[nt][0] - mn0);
            float p1 = ex2(sacc[nt][1] - mn0);
            float p2 = ex2(sacc[nt][2] - mn1);
            float p3 = ex2(sacc[nt][3] - mn1);
            sum0 += p0 + p1;
            sum1 += p2 + p3;
            const int c = nt * 8 + 2 * tig;
            prow[(gid) * AT_PSTR + c]         = f2tf32(p0);
            prow[(gid) * AT_PSTR + c + 1]     = f2tf32(p1);
            prow[(gid + 8) * AT_PSTR + c]     = f2tf32(p2);
            prow[(gid + 8) * AT_PSTR + c + 1] = f2tf32(p3);
            oacc[nt][0] *= corr0;
            oacc[nt][1] *= corr0;
            oacc[nt][2] *= corr1;
            oacc[nt][3] *= corr1;
        }
        sum0 += __shfl_xor_sync(0xffffffffu, sum0, 1);
        sum0 += __shfl_xor_sync(0xffffffffu, sum0, 2);
        sum1 += __shfl_xor_sync(0xffffffffu, sum1, 1);
        sum1 += __shfl_xor_sync(0xffffffffu, sum1, 2);
        l0 = l0 * corr0 + sum0;
        l1 = l1 * corr1 + sum1;

        __syncwarp();

        // ---- O += P @ V ----
#pragma unroll
        for (int kk = 0; kk < 8; kk++) {
            uint32_t afr[4];
            afr[0] = prow[gid * AT_PSTR + kk * 8 + tig];
            afr[1] = prow[(gid + 8) * AT_PSTR + kk * 8 + tig];
            afr[2] = prow[gid * AT_PSTR + kk * 8 + tig + 4];
            afr[3] = prow[(gid + 8) * AT_PSTR + kk * 8 + tig + 4];
            uint32_t bfr[8][2];
#pragma unroll
            for (int nt = 0; nt < 8; nt++) {
                const int d = nt * 8 + gid;
                bfr[nt][0] = vs[(kk * 8 + tig) * AT_VSTR + d];
                bfr[nt][1] = vs[(kk * 8 + tig + 4) * AT_VSTR + d];
            }
#pragma unroll
            for (int nt = 0; nt < 8; nt++)
                mma_tf32(oacc[nt], afr, bfr[nt]);
        }
        __syncthreads();
    }

    // ---- normalize, tf32-round (feeds O-proj), write out ----
    const float inv0 = 1.f / l0;
    const float inv1 = 1.f / l1;
    float* olo = vals + (size_t)(b * SS + q0 + wid * 16 + gid) * DD + h * HDIM;
    float* ohi = olo + 8 * DD;
#pragma unroll
    for (int nt = 0; nt < 8; nt++) {
        const int c = nt * 8 + 2 * tig;
        float2 r0, r1;
        r0.x = __uint_as_float(f2tf32(oacc[nt][0] * inv0));
        r0.y = __uint_as_float(f2tf32(oacc[nt][1] * inv0));
        r1.x = __uint_as_float(f2tf32(oacc[nt][2] * inv1));
        r1.y = __uint_as_float(f2tf32(oacc[nt][3] * inv1));
        *(float2*)(olo + c) = r0;
        *(float2*)(ohi + c) = r1;
    }
}

// ---------------------------------------------------------------------------
// Launch
// ---------------------------------------------------------------------------
extern "C" void kernel_launch(void* const* d_in, const int* in_sizes, int n_in,
                              void* d_out, int out_size)
{
    const float* x      = (const float*)d_in[0];
    const float* w_qkv  = (const float*)d_in[1];
    const float* b_qkv  = (const float*)d_in[2];
    const float* w_o    = (const float*)d_in[3];
    const float* b_o    = (const float*)d_in[4];
    float* out = (float*)d_out;

    float *qkv_buf, *vals_buf, *xc, *wqc, *woc;
    cudaGetSymbolAddress((void**)&qkv_buf, g_qkv);
    cudaGetSymbolAddress((void**)&vals_buf, g_vals);
    cudaGetSymbolAddress((void**)&xc,  g_xc);
    cudaGetSymbolAddress((void**)&wqc, g_wqc);
    cudaGetSymbolAddress((void**)&woc, g_woc);

    cudaFuncSetAttribute(gemm_mma_kernel,
                         cudaFuncAttributeMaxDynamicSharedMemorySize,
                         GEMM_SMEM_BYTES);
    cudaFuncSetAttribute(attn_mma_kernel,
                         cudaFuncAttributeMaxDynamicSharedMemorySize,
                         ATT_SMEM_BYTES);

    // 0) tf32 pre-conversion of inputs
    {
        int n4x = M_ROWS * DIN / 4;
        int n4q = QKV_N * DIN / 4;
        int n4o = DD * DD / 4;
        tf32_cvt_kernel<<<(n4x + 255) / 256, 256>>>((const float4*)x,     (float4*)xc,  n4x);
        tf32_cvt_kernel<<<(n4q + 255) / 256, 256>>>((const float4*)w_qkv, (float4*)wqc, n4q);
        tf32_cvt_kernel<<<(n4o + 255) / 256, 256>>>((const float4*)w_o,   (float4*)woc, n4o);
    }

    // 1) QKV projection -> g_qkv (tf32-rounded output)
    {
        dim3 grid(QKV_N / 128, M_ROWS / 128);
        gemm_mma_kernel<<<grid, 256, GEMM_SMEM_BYTES>>>(
            xc, wqc, b_qkv, qkv_buf, M_ROWS, QKV_N, DIN, 1);
    }

    // 2) Attention -> g_vals (tf32-rounded output)
    {
        dim3 grid(SS / 128, HH, BB);
        attn_mma_kernel<<<grid, 256, ATT_SMEM_BYTES>>>(qkv_buf, vals_buf);
    }

    // 3) Output projection -> out (plain fp32)
    {
        dim3 grid(DD / 128, M_ROWS / 128);
        gemm_mma_kernel<<<grid, 256, GEMM_SMEM_BYTES>>>(
            vals_buf, woc, b_o, out, M_ROWS, DD, DIN, 0);
    }
}

// round 6
// speedup vs baseline: 4.5494x; 1.0670x over previous
#include <cuda_runtime.h>
#include <cuda_bf16.h>
#include <cstdint>
#include <math.h>

// Problem constants
#define BB   2
#define SS   2048
#define DIN  1024
#define DD   1024
#define HH   16
#define HDIM 64
#define M_ROWS (BB * SS)      // 4096
#define QKV_N  (3 * DD)       // 3072

// Scratch (tf32-bit-pattern fp32 buffers)
__device__ float g_qkv [M_ROWS * QKV_N];
__device__ float g_vals[M_ROWS * DD];
__device__ float g_xc  [M_ROWS * DIN];
__device__ float g_wqc [QKV_N * DIN];
__device__ float g_woc [DD * DD];

// ---------------------------------------------------------------------------
// Helpers
// ---------------------------------------------------------------------------
__device__ __forceinline__ uint32_t smem_u32(const void* p) {
    uint32_t a;
    asm("{ .reg .u64 t; cvta.to.shared.u64 t, %1; cvt.u32.u64 %0, t; }"
        : "=r"(a) : "l"(p));
    return a;
}

__device__ __forceinline__ uint32_t f2tf32(float f) {
    uint32_t u;
    asm("cvt.rna.tf32.f32 %0, %1;" : "=r"(u) : "f"(f));
    return u;
}

__device__ __forceinline__ float ex2(float x) {
    float r;
    asm("ex2.approx.f32 %0, %1;" : "=f"(r) : "f"(x));
    return r;
}

__device__ __forceinline__ void mma_tf32(float* d, const uint32_t* a, const uint32_t* b) {
    asm volatile(
        "mma.sync.aligned.m16n8k8.row.col.f32.tf32.tf32.f32 "
        "{%0,%1,%2,%3}, {%4,%5,%6,%7}, {%8,%9}, {%0,%1,%2,%3};"
        : "+f"(d[0]), "+f"(d[1]), "+f"(d[2]), "+f"(d[3])
        : "r"(a[0]), "r"(a[1]), "r"(a[2]), "r"(a[3]),
          "r"(b[0]), "r"(b[1]));
}

// ---------------------------------------------------------------------------
// Elementwise tf32 pre-conversion
// ---------------------------------------------------------------------------
__global__ __launch_bounds__(256) void tf32_cvt_kernel(
    const float4* __restrict__ s, float4* __restrict__ d, int n4)
{
    int i = blockIdx.x * blockDim.x + threadIdx.x;
    if (i < n4) {
        float4 v = s[i];
        uint4 o;
        o.x = f2tf32(v.x);
        o.y = f2tf32(v.y);
        o.z = f2tf32(v.z);
        o.w = f2tf32(v.w);
        ((uint4*)d)[i] = o;
    }
}

// ---------------------------------------------------------------------------
// mma.sync tf32 GEMM, pre-converted operands, 3-stage cp.async pipeline,
// ONE syncthreads per BK-iteration. C = A @ Bw^T + bias.
// 128x128 CTA, BK=32, 256 thr (8 warps 2x4), warp tile 64x32.
// ---------------------------------------------------------------------------
#define GEMM_BK     32
#define LDS_STR     36
#define TILE_FL     (128 * LDS_STR)            // 4608 floats
#define GM_STAGES   3
#define GEMM_SMEM_BYTES (2 * GM_STAGES * TILE_FL * 4)   // 110592

__global__ __launch_bounds__(256, 2) void gemm_mma_kernel(
    const float* __restrict__ A, const float* __restrict__ Bw,
    const float* __restrict__ bias, float* __restrict__ C,
    int M, int N, int K, int cvt_out)
{
    extern __shared__ float smf[];
    const uint32_t sb = smem_u32(smf);
    const int tid  = threadIdx.x;
    const int wid  = tid >> 5;
    const int lane = tid & 31;
    const int gid  = lane >> 2;
    const int tig  = lane & 3;
    const int wm   = (wid >> 2) * 64;
    const int wn   = (wid & 3) * 32;
    const int m0 = blockIdx.y * 128;
    const int n0 = blockIdx.x * 128;

    float acc[4][4][4];
#pragma unroll
    for (int i = 0; i < 4; i++)
#pragma unroll
        for (int j = 0; j < 4; j++)
#pragma unroll
            for (int r = 0; r < 4; r++) acc[i][j][r] = 0.f;

    const int KCH = K / GEMM_BK;

    auto load_stage = [&](int chunk, int stage) {
        const int k0 = chunk * GEMM_BK;
        const uint32_t a_s = sb + stage * (TILE_FL * 4);
        const uint32_t b_s = sb + GM_STAGES * (TILE_FL * 4) + stage * (TILE_FL * 4);
        const float* ag = A + (size_t)m0 * K + k0;
        const float* bg = Bw + (size_t)n0 * K + k0;
#pragma unroll
        for (int it = 0; it < 4; it++) {
            int idx = it * 256 + tid;
            int row = idx >> 3;
            int c4  = (idx & 7) * 4;
            uint32_t doff = (uint32_t)(row * LDS_STR + c4) * 4;
            asm volatile("cp.async.cg.shared.global [%0], [%1], 16;"
                         :: "r"(a_s + doff), "l"(ag + (size_t)row * K + c4));
            asm volatile("cp.async.cg.shared.global [%0], [%1], 16;"
                         :: "r"(b_s + doff), "l"(bg + (size_t)row * K + c4));
        }
    };

    load_stage(0, 0);
    asm volatile("cp.async.commit_group;" ::: "memory");
    load_stage(1, 1);
    asm volatile("cp.async.commit_group;" ::: "memory");

    int cstage = 0;   // stage of chunk j
    int lstage = 2;   // stage for chunk j+2
    for (int j = 0; j < KCH; j++) {
        if (j + 1 < KCH) {
            asm volatile("cp.async.wait_group 1;" ::: "memory");
        } else {
            asm volatile("cp.async.wait_group 0;" ::: "memory");
        }
        __syncthreads();   // all warps done with the stage we're about to load into
        if (j + 2 < KCH) {
            load_stage(j + 2, lstage);
            asm volatile("cp.async.commit_group;" ::: "memory");
        }

        const uint32_t* as = (const uint32_t*)(smf + cstage * TILE_FL);
        const uint32_t* bs = (const uint32_t*)(smf + GM_STAGES * TILE_FL + cstage * TILE_FL);

#pragma unroll
        for (int kk = 0; kk < 4; kk++) {
            const int kb = kk * 8 + tig;
            uint32_t afr[4][4];
#pragma unroll
            for (int mt = 0; mt < 4; mt++) {
                const int r = wm + mt * 16 + gid;
                afr[mt][0] = as[r * LDS_STR + kb];
                afr[mt][1] = as[(r + 8) * LDS_STR + kb];
                afr[mt][2] = as[r * LDS_STR + kb + 4];
                afr[mt][3] = as[(r + 8) * LDS_STR + kb + 4];
            }
            uint32_t bfr[4][2];
#pragma unroll
            for (int nt = 0; nt < 4; nt++) {
                const int c = wn + nt * 8 + gid;
                bfr[nt][0] = bs[c * LDS_STR + kb];
                bfr[nt][1] = bs[c * LDS_STR + kb + 4];
            }
#pragma unroll
            for (int mt = 0; mt < 4; mt++)
#pragma unroll
                for (int nt = 0; nt < 4; nt++)
                    mma_tf32(acc[mt][nt], afr[mt], bfr[nt]);
        }
        cstage = (cstage == GM_STAGES - 1) ? 0 : cstage + 1;
        lstage = (lstage == GM_STAGES - 1) ? 0 : lstage + 1;
    }

#pragma unroll
    for (int mt = 0; mt < 4; mt++) {
        const int row = m0 + wm + mt * 16 + gid;
#pragma unroll
        for (int nt = 0; nt < 4; nt++) {
            const int col = n0 + wn + nt * 8 + tig * 2;
            float2 bv = *(const float2*)(bias + col);
            float2 o0, o1;
            o0.x = acc[mt][nt][0] + bv.x;
            o0.y = acc[mt][nt][1] + bv.y;
            o1.x = acc[mt][nt][2] + bv.x;
            o1.y = acc[mt][nt][3] + bv.y;
            if (cvt_out) {
                o0.x = __uint_as_float(f2tf32(o0.x));
                o0.y = __uint_as_float(f2tf32(o0.y));
                o1.x = __uint_as_float(f2tf32(o1.x));
                o1.y = __uint_as_float(f2tf32(o1.y));
            }
            *(float2*)(C + (size_t)row * N + col) = o0;
            *(float2*)(C + (size_t)(row + 8) * N + col) = o1;
        }
    }
}

// ---------------------------------------------------------------------------
// Flash attention, mma.sync tf32, register-resident P (no P smem):
// S C-fragment is reused directly as the P@V A-fragment, with V rows read in
// the matching permuted order (k-sum is permutation invariant):
//   logical slot l<4 -> key 8kk+2l ; l>=4 -> key 8kk+2(l-4)+1.
// SMEM = K,V double-buffered only (~70KB) -> 2 CTAs/SM.
// ---------------------------------------------------------------------------
#define AT_KSTR 68
#define AT_VSTR 68
#define AT_KFL  (64 * AT_KSTR)
#define AT_VFL  (64 * AT_VSTR)
#define AT_V0   (2 * AT_KFL)
#define ATT_SMEM_FLOATS (AT_V0 + 2 * AT_VFL)
#define ATT_SMEM_BYTES  (ATT_SMEM_FLOATS * 4)   // 69632

__global__ __launch_bounds__(256, 2) void attn_mma_kernel(
    const float* __restrict__ qkv, float* __restrict__ vals)
{
    extern __shared__ float fsm[];
    const uint32_t sb = smem_u32(fsm);
    const uint32_t* k_sm = (const uint32_t*)fsm;
    const uint32_t* v_sm = (const uint32_t*)(fsm + AT_V0);

    const int tid  = threadIdx.x;
    const int wid  = tid >> 5;
    const int lane = tid & 31;
    const int gid  = lane >> 2;
    const int tig  = lane & 3;
    const int b  = blockIdx.z;
    const int h  = blockIdx.y;
    const int q0 = blockIdx.x * 128;

    const float qscale = 0.125f * 1.4426950408889634f;

    uint32_t qf[8][4];
    {
        const float* qlo = qkv + (size_t)(b * SS + q0 + wid * 16 + gid) * QKV_N + h * 192;
        const float* qhi = qlo + 8 * QKV_N;
#pragma unroll
        for (int kk = 0; kk < 8; kk++) {
            const int c = kk * 8 + tig;
            qf[kk][0] = f2tf32(qlo[c] * qscale);
            qf[kk][1] = f2tf32(qhi[c] * qscale);
            qf[kk][2] = f2tf32(qlo[c + 4] * qscale);
            qf[kk][3] = f2tf32(qhi[c + 4] * qscale);
        }
    }

    const float* kvbase = qkv + (size_t)(b * SS) * QKV_N + h * 192 + 64;
    auto load_tile = [&](int kt) {
        const int stage = kt & 1;
        const float* src = kvbase + (size_t)kt * 64 * QKV_N;
        const uint32_t kdst = sb + (stage * AT_KFL) * 4;
        const uint32_t vdst = sb + (AT_V0 + stage * AT_VFL) * 4;
#pragma unroll
        for (int it = 0; it < 4; it++) {
            int idx = it * 256 + tid;
            int row = idx >> 4;
            int c4  = (idx & 15) * 4;
            const float* g = src + (size_t)row * QKV_N + c4;
            asm volatile("cp.async.cg.shared.global [%0], [%1], 16;"
                         :: "r"(kdst + (uint32_t)(row * AT_KSTR + c4) * 4), "l"(g));
            asm volatile("cp.async.cg.shared.global [%0], [%1], 16;"
                         :: "r"(vdst + (uint32_t)(row * AT_VSTR + c4) * 4), "l"(g + 64));
        }
    };

    float m0 = -1e30f, m1 = -1e30f, l0 = 0.f, l1 = 0.f;
    float oacc[8][4];
#pragma unroll
    for (int nt = 0; nt < 8; nt++)
#pragma unroll
        for (int r = 0; r < 4; r++) oacc[nt][r] = 0.f;

    load_tile(0);
    asm volatile("cp.async.commit_group;" ::: "memory");

    const int NT = SS / 64;
    for (int kt = 0; kt < NT; kt++) {
        asm volatile("cp.async.wait_group 0;" ::: "memory");  // tile kt arrived
        __syncthreads();                                       // stage (kt+1)&1 free
        if (kt + 1 < NT) {
            load_tile(kt + 1);
            asm volatile("cp.async.commit_group;" ::: "memory");
        }

        const int stage = kt & 1;
        const uint32_t* ks = k_sm + stage * AT_KFL;
        const uint32_t* vs = v_sm + stage * AT_VFL;

        // ---- S = Q @ K^T ----
        float sacc[8][4];
#pragma unroll
        for (int nt = 0; nt < 8; nt++)
#pragma unroll
            for (int r = 0; r < 4; r++) sacc[nt][r] = 0.f;

#pragma unroll
        for (int kk = 0; kk < 8; kk++) {
            const int kb = kk * 8 + tig;
            uint32_t bfr[8][2];
#pragma unroll
            for (int nt = 0; nt < 8; nt++) {
                const int key = nt * 8 + gid;
                bfr[nt][0] = ks[key * AT_KSTR + kb];
                bfr[nt][1] = ks[key * AT_KSTR + kb + 4];
            }
#pragma unroll
            for (int nt = 0; nt < 8; nt++)
                mma_tf32(sacc[nt], qf[kk], bfr[nt]);
        }

        // ---- online softmax (log2 domain) ----
        float tmax0 = -1e30f, tmax1 = -1e30f;
#pragma unroll
        for (int nt = 0; nt < 8; nt++) {
            tmax0 = fmaxf(tmax0, fmaxf(sacc[nt][0], sacc[nt][1]));
            tmax1 = fmaxf(tmax1, fmaxf(sacc[nt][2], sacc[nt][3]));
        }
        tmax0 = fmaxf(tmax0, __shfl_xor_sync(0xffffffffu, tmax0, 1));
        tmax0 = fmaxf(tmax0, __shfl_xor_sync(0xffffffffu, tmax0, 2));
        tmax1 = fmaxf(tmax1, __shfl_xor_sync(0xffffffffu, tmax1, 1));
        tmax1 = fmaxf(tmax1, __shfl_xor_sync(0xffffffffu, tmax1, 2));

        const float mn0 = fmaxf(m0, tmax0);
        const float mn1 = fmaxf(m1, tmax1);
        const float corr0 = ex2(m0 - mn0);
        const float corr1 = ex2(m1 - mn1);
        m0 = mn0; m1 = mn1;

        // P fragments built in-place over sacc registers:
        // pf[nt] = { cvt(p0), cvt(p2), cvt(p1), cvt(p3) }  (A-frag row/col map)
        uint32_t pf[8][4];
        float sum0 = 0.f, sum1 = 0.f;
#pragma unroll
        for (int nt = 0; nt < 8; nt++) {
            float p0 = ex2(sacc[nt][0] - mn0);
            float p1 = ex2(sacc[nt][1] - mn0);
            float p2 = ex2(sacc[nt][2] - mn1);
            float p3 = ex2(sacc[nt][3] - mn1);
            sum0 += p0 + p1;
            sum1 += p2 + p3;
            pf[nt][0] = f2tf32(p0);
            pf[nt][1] = f2tf32(p2);
            pf[nt][2] = f2tf32(p1);
            pf[nt][3] = f2tf32(p3);
            oacc[nt][0] *= corr0;
            oacc[nt][1] *= corr0;
            oacc[nt][2] *= corr1;
            oacc[nt][3] *= corr1;
        }
        sum0 += __shfl_xor_sync(0xffffffffu, sum0, 1);
        sum0 += __shfl_xor_sync(0xffffffffu, sum0, 2);
        sum1 += __shfl_xor_sync(0xffffffffu, sum1, 1);
        sum1 += __shfl_xor_sync(0xffffffffu, sum1, 2);
        l0 = l0 * corr0 + sum0;
        l1 = l1 * corr1 + sum1;

        // ---- O += P @ V (V rows permuted to match C->A frag reuse) ----
#pragma unroll
        for (int kk = 0; kk < 8; kk++) {
            uint32_t bfr[8][2];
            const int r0 = (kk * 8 + 2 * tig) * AT_VSTR;
            const int r1 = r0 + AT_VSTR;
#pragma unroll
            for (int nt = 0; nt < 8; nt++) {
                const int d = nt * 8 + gid;
                bfr[nt][0] = vs[r0 + d];
                bfr[nt][1] = vs[r1 + d];
            }
#pragma unroll
            for (int nt = 0; nt < 8; nt++)
                mma_tf32(oacc[nt], pf[kk], bfr[nt]);
        }
    }

    // ---- normalize, tf32-round (feeds O-proj), write out ----
    const float inv0 = 1.f / l0;
    const float inv1 = 1.f / l1;
    float* olo = vals + (size_t)(b * SS + q0 + wid * 16 + gid) * DD + h * HDIM;
    float* ohi = olo + 8 * DD;
#pragma unroll
    for (int nt = 0; nt < 8; nt++) {
        const int c = nt * 8 + 2 * tig;
        float2 r0, r1;
        r0.x = __uint_as_float(f2tf32(oacc[nt][0] * inv0));
        r0.y = __uint_as_float(f2tf32(oacc[nt][1] * inv0));
        r1.x = __uint_as_float(f2tf32(oacc[nt][2] * inv1));
        r1.y = __uint_as_float(f2tf32(oacc[nt][3] * inv1));
        *(float2*)(olo + c) = r0;
        *(float2*)(ohi + c) = r1;
    }
}

// ---------------------------------------------------------------------------
// Launch
// ---------------------------------------------------------------------------
extern "C" void kernel_launch(void* const* d_in, const int* in_sizes, int n_in,
                              void* d_out, int out_size)
{
    const float* x      = (const float*)d_in[0];
    const float* w_qkv  = (const float*)d_in[1];
    const float* b_qkv  = (const float*)d_in[2];
    const float* w_o    = (const float*)d_in[3];
    const float* b_o    = (const float*)d_in[4];
    float* out = (float*)d_out;

    float *qkv_buf, *vals_buf, *xc, *wqc, *woc;
    cudaGetSymbolAddress((void**)&qkv_buf, g_qkv);
    cudaGetSymbolAddress((void**)&vals_buf, g_vals);
    cudaGetSymbolAddress((void**)&xc,  g_xc);
    cudaGetSymbolAddress((void**)&wqc, g_wqc);
    cudaGetSymbolAddress((void**)&woc, g_woc);

    cudaFuncSetAttribute(gemm_mma_kernel,
                         cudaFuncAttributeMaxDynamicSharedMemorySize,
                         GEMM_SMEM_BYTES);
    cudaFuncSetAttribute(attn_mma_kernel,
                         cudaFuncAttributeMaxDynamicSharedMemorySize,
                         ATT_SMEM_BYTES);

    // 0) tf32 pre-conversion of inputs
    {
        int n4x = M_ROWS * DIN / 4;
        int n4q = QKV_N * DIN / 4;
        int n4o = DD * DD / 4;
        tf32_cvt_kernel<<<(n4x + 255) / 256, 256>>>((const float4*)x,     (float4*)xc,  n4x);
        tf32_cvt_kernel<<<(n4q + 255) / 256, 256>>>((const float4*)w_qkv, (float4*)wqc, n4q);
        tf32_cvt_kernel<<<(n4o + 255) / 256, 256>>>((const float4*)w_o,   (float4*)woc, n4o);
    }

    // 1) QKV projection -> g_qkv (tf32-rounded output)
    {
        dim3 grid(QKV_N / 128, M_ROWS / 128);
        gemm_mma_kernel<<<grid, 256, GEMM_SMEM_BYTES>>>(
            xc, wqc, b_qkv, qkv_buf, M_ROWS, QKV_N, DIN, 1);
    }

    // 2) Attention -> g_vals (tf32-rounded output)
    {
        dim3 grid(SS / 128, HH, BB);
        attn_mma_kernel<<<grid, 256, ATT_SMEM_BYTES>>>(qkv_buf, vals_buf);
    }

    // 3) Output projection -> out (plain fp32)
    {
        dim3 grid(DD / 128, M_ROWS / 128);
        gemm_mma_kernel<<<grid, 256, GEMM_SMEM_BYTES>>>(
            vals_buf, woc, b_o, out, M_ROWS, DD, DIN, 0);
    }
}

// round 7
// speedup vs baseline: 5.0714x; 1.1147x over previous
#include <cuda_runtime.h>
#include <cuda_bf16.h>
#include <cstdint>
#include <math.h>

// Problem constants
#define BB   2
#define SS   2048
#define DIN  1024
#define DD   1024
#define HH   16
#define HDIM 64
#define M_ROWS (BB * SS)      // 4096
#define QKV_N  (3 * DD)       // 3072

// Scratch
__device__ float g_qkv  [M_ROWS * QKV_N];   // qkv row-major, tf32-rounded
__device__ float g_vals [M_ROWS * DD];      // attention out, row-major
__device__ float g_xc   [M_ROWS * DIN];     // x, fragment-packed
__device__ float g_valsp[M_ROWS * DD];      // vals, fragment-packed
__device__ float g_wqc  [QKV_N * DIN];      // w_qkv, fragment-packed
__device__ float g_woc  [DD * DD];          // w_o, fragment-packed

// ---------------------------------------------------------------------------
// Helpers
// ---------------------------------------------------------------------------
__device__ __forceinline__ uint32_t smem_u32(const void* p) {
    uint32_t a;
    asm("{ .reg .u64 t; cvta.to.shared.u64 t, %1; cvt.u32.u64 %0, t; }"
        : "=r"(a) : "l"(p));
    return a;
}

__device__ __forceinline__ uint32_t f2tf32(float f) {
    uint32_t u;
    asm("cvt.rna.tf32.f32 %0, %1;" : "=r"(u) : "f"(f));
    return u;
}

__device__ __forceinline__ float ex2(float x) {
    float r;
    asm("ex2.approx.f32 %0, %1;" : "=f"(r) : "f"(x));
    return r;
}

__device__ __forceinline__ void mma_tf32(float* d, const uint32_t* a, const uint32_t* b) {
    asm("mma.sync.aligned.m16n8k8.row.col.f32.tf32.tf32.f32 "
        "{%0,%1,%2,%3}, {%4,%5,%6,%7}, {%8,%9}, {%0,%1,%2,%3};"
        : "+f"(d[0]), "+f"(d[1]), "+f"(d[2]), "+f"(d[3])
        : "r"(a[0]), "r"(a[1]), "r"(a[2]), "r"(a[3]),
          "r"(b[0]), "r"(b[1]));
}

// ---------------------------------------------------------------------------
// Fragment repack kernels.  One block = one 128x32 tile.
// A-layout (m-operand): float4 chunk q in [0,1024):
//   grp=(q>>7) (wm2*4+mt), kk=(q>>5)&3, lane=q&31, gid=lane>>2, tig=lane&3
//   chunk = { A[r0][kb], A[r0+8][kb], A[r0][kb+4], A[r0+8][kb+4] },
//   r0=(grp>>2)*64+(grp&3)*16+gid, kb=kk*8+tig
// B-layout (n-operand): float2 chunk q in [0,2048):
//   grp=(q>>7) (wgrp*4+nt, 0..15), kk=(q>>5)&3, lane=q&31
//   chunk = { B[n][kb], B[n][kb+4] }, n=grp*8+(lane>>2), kb=kk*8+(lane&3)
// Both apply tf32 rounding.
// ---------------------------------------------------------------------------
__global__ __launch_bounds__(256) void pack_a_kernel(
    const float* __restrict__ src, float* __restrict__ dst, int K)
{
    __shared__ float sm[128 * 33];
    const int tid = threadIdx.x;
    const int kt  = blockIdx.x % (K / 32);
    const int mt  = blockIdx.x / (K / 32);
    const float* g = src + (size_t)(mt * 128) * K + kt * 32;
#pragma unroll
    for (int it = 0; it < 4; it++) {
        int idx = it * 256 + tid;
        int r = idx >> 3;
        int c4 = (idx & 7) * 4;
        float4 v = *(const float4*)(g + (size_t)r * K + c4);
        sm[r * 33 + c4 + 0] = __uint_as_float(f2tf32(v.x));
        sm[r * 33 + c4 + 1] = __uint_as_float(f2tf32(v.y));
        sm[r * 33 + c4 + 2] = __uint_as_float(f2tf32(v.z));
        sm[r * 33 + c4 + 3] = __uint_as_float(f2tf32(v.w));
    }
    __syncthreads();
    float4* o = (float4*)(dst + (size_t)blockIdx.x * 4096);
#pragma unroll
    for (int it = 0; it < 4; it++) {
        int q = it * 256 + tid;
        int grp = q >> 7;
        int kk = (q >> 5) & 3;
        int lane = q & 31;
        int gid = lane >> 2;
        int tig = lane & 3;
        int r0 = (grp >> 2) * 64 + (grp & 3) * 16 + gid;
        int kb = kk * 8 + tig;
        float4 w;
        w.x = sm[r0 * 33 + kb];
        w.y = sm[(r0 + 8) * 33 + kb];
        w.z = sm[r0 * 33 + kb + 4];
        w.w = sm[(r0 + 8) * 33 + kb + 4];
        o[q] = w;
    }
}

__global__ __launch_bounds__(256) void pack_b_kernel(
    const float* __restrict__ src, float* __restrict__ dst, int K)
{
    __shared__ float sm[128 * 33];
    const int tid = threadIdx.x;
    const int kt  = blockIdx.x % (K / 32);
    const int nt  = blockIdx.x / (K / 32);
    const float* g = src + (size_t)(nt * 128) * K + kt * 32;
#pragma unroll
    for (int it = 0; it < 4; it++) {
        int idx = it * 256 + tid;
        int r = idx >> 3;
        int c4 = (idx & 7) * 4;
        float4 v = *(const float4*)(g + (size_t)r * K + c4);
        sm[r * 33 + c4 + 0] = __uint_as_float(f2tf32(v.x));
        sm[r * 33 + c4 + 1] = __uint_as_float(f2tf32(v.y));
        sm[r * 33 + c4 + 2] = __uint_as_float(f2tf32(v.z));
        sm[r * 33 + c4 + 3] = __uint_as_float(f2tf32(v.w));
    }
    __syncthreads();
    float2* o = (float2*)(dst + (size_t)blockIdx.x * 4096);
#pragma unroll
    for (int it = 0; it < 8; it++) {
        int q = it * 256 + tid;
        int grp = q >> 7;
        int kk = (q >> 5) & 3;
        int lane = q & 31;
        int n = grp * 8 + (lane >> 2);
        int kb = kk * 8 + (lane & 3);
        float2 w;
        w.x = sm[n * 33 + kb];
        w.y = sm[n * 33 + kb + 4];
        o[q] = w;
    }
}

// ---------------------------------------------------------------------------
// mma.sync tf32 GEMM on fragment-packed operands.
// A, Bw: fragment-packed tiles of 4096 floats, tile (i, kt) at
// (i*(K/32)+kt)*4096.  Mainloop frag loads: LDS.128 (A) / LDS.64 (B).
// 128x128 CTA, BK=32, 256 thr (8 warps 2x4), warp tile 64x32, 3-stage pipe.
// ---------------------------------------------------------------------------
#define TILE_FL     4096
#define GM_STAGES   3
#define GEMM_SMEM_BYTES (2 * GM_STAGES * TILE_FL * 4)   // 98304

__global__ __launch_bounds__(256, 2) void gemm_mma_kernel(
    const float* __restrict__ A, const float* __restrict__ Bw,
    const float* __restrict__ bias, float* __restrict__ C,
    int M, int N, int K, int cvt_out)
{
    extern __shared__ float smf[];
    const uint32_t sb = smem_u32(smf);
    const int tid  = threadIdx.x;
    const int wid  = tid >> 5;
    const int lane = tid & 31;
    const int gid  = lane >> 2;
    const int tig  = lane & 3;
    const int wm2  = wid >> 2;        // 0..1
    const int wgrp = wid & 3;         // 0..3
    const int m0 = blockIdx.y * 128;
    const int n0 = blockIdx.x * 128;
    const int KT = K / 32;

    float acc[4][4][4];
#pragma unroll
    for (int i = 0; i < 4; i++)
#pragma unroll
        for (int j = 0; j < 4; j++)
#pragma unroll
            for (int r = 0; r < 4; r++) acc[i][j][r] = 0.f;

    auto load_stage = [&](int chunk, int stage) {
        const float* ag = A + ((size_t)blockIdx.y * KT + chunk) * TILE_FL;
        const float* bg = Bw + ((size_t)blockIdx.x * KT + chunk) * TILE_FL;
        const uint32_t a_s = sb + stage * (TILE_FL * 4);
        const uint32_t b_s = sb + (GM_STAGES + stage) * (TILE_FL * 4);
#pragma unroll
        for (int it = 0; it < 4; it++) {
            int idx = it * 256 + tid;
            asm volatile("cp.async.cg.shared.global [%0], [%1], 16;"
                         :: "r"(a_s + idx * 16), "l"(ag + idx * 4));
            asm volatile("cp.async.cg.shared.global [%0], [%1], 16;"
                         :: "r"(b_s + idx * 16), "l"(bg + idx * 4));
        }
    };

    load_stage(0, 0);
    asm volatile("cp.async.commit_group;" ::: "memory");
    load_stage(1, 1);
    asm volatile("cp.async.commit_group;" ::: "memory");

    int cstage = 0;
    int lstage = 2;
    for (int j = 0; j < KT; j++) {
        if (j + 1 < KT) {
            asm volatile("cp.async.wait_group 1;" ::: "memory");
        } else {
            asm volatile("cp.async.wait_group 0;" ::: "memory");
        }
        __syncthreads();
        if (j + 2 < KT) {
            load_stage(j + 2, lstage);
            asm volatile("cp.async.commit_group;" ::: "memory");
        }

        const float4* at4 = (const float4*)(smf + cstage * TILE_FL);
        const float2* bt2 = (const float2*)(smf + (GM_STAGES + cstage) * TILE_FL);

#pragma unroll
        for (int kk = 0; kk < 4; kk++) {
            float4 afr[4];
#pragma unroll
            for (int mt = 0; mt < 4; mt++)
                afr[mt] = at4[(((wm2 * 4 + mt) * 4 + kk) << 5) + lane];
            float2 bfr[4];
#pragma unroll
            for (int nt = 0; nt < 4; nt++)
                bfr[nt] = bt2[(((wgrp * 4 + nt) * 4 + kk) << 5) + lane];
#pragma unroll
            for (int mt = 0; mt < 4; mt++)
#pragma unroll
                for (int nt = 0; nt < 4; nt++)
                    mma_tf32(acc[mt][nt],
                             (const uint32_t*)&afr[mt],
                             (const uint32_t*)&bfr[nt]);
        }
        cstage = (cstage == GM_STAGES - 1) ? 0 : cstage + 1;
        lstage = (lstage == GM_STAGES - 1) ? 0 : lstage + 1;
    }

#pragma unroll
    for (int mt = 0; mt < 4; mt++) {
        const int row = m0 + wm2 * 64 + mt * 16 + gid;
#pragma unroll
        for (int nt = 0; nt < 4; nt++) {
            const int col = n0 + wgrp * 32 + nt * 8 + tig * 2;
            float2 bv = *(const float2*)(bias + col);
            float2 o0, o1;
            o0.x = acc[mt][nt][0] + bv.x;
            o0.y = acc[mt][nt][1] + bv.y;
            o1.x = acc[mt][nt][2] + bv.x;
            o1.y = acc[mt][nt][3] + bv.y;
            if (cvt_out) {
                o0.x = __uint_as_float(f2tf32(o0.x));
                o0.y = __uint_as_float(f2tf32(o0.y));
                o1.x = __uint_as_float(f2tf32(o1.x));
                o1.y = __uint_as_float(f2tf32(o1.y));
            }
            *(float2*)(C + (size_t)row * N + col) = o0;
            *(float2*)(C + (size_t)(row + 8) * N + col) = o1;
        }
    }
}

// ---------------------------------------------------------------------------
// Flash attention, mma.sync tf32, register-resident P (unchanged from r6).
// ---------------------------------------------------------------------------
#define AT_KSTR 68
#define AT_VSTR 68
#define AT_KFL  (64 * AT_KSTR)
#define AT_VFL  (64 * AT_VSTR)
#define AT_V0   (2 * AT_KFL)
#define ATT_SMEM_FLOATS (AT_V0 + 2 * AT_VFL)
#define ATT_SMEM_BYTES  (ATT_SMEM_FLOATS * 4)   // 69632

__global__ __launch_bounds__(256, 2) void attn_mma_kernel(
    const float* __restrict__ qkv, float* __restrict__ vals)
{
    extern __shared__ float fsm[];
    const uint32_t sb = smem_u32(fsm);
    const uint32_t* k_sm = (const uint32_t*)fsm;
    const uint32_t* v_sm = (const uint32_t*)(fsm + AT_V0);

    const int tid  = threadIdx.x;
    const int wid  = tid >> 5;
    const int lane = tid & 31;
    const int gid  = lane >> 2;
    const int tig  = lane & 3;
    const int b  = blockIdx.z;
    const int h  = blockIdx.y;
    const int q0 = blockIdx.x * 128;

    const float qscale = 0.125f * 1.4426950408889634f;

    uint32_t qf[8][4];
    {
        const float* qlo = qkv + (size_t)(b * SS + q0 + wid * 16 + gid) * QKV_N + h * 192;
        const float* qhi = qlo + 8 * QKV_N;
#pragma unroll
        for (int kk = 0; kk < 8; kk++) {
            const int c = kk * 8 + tig;
            qf[kk][0] = f2tf32(qlo[c] * qscale);
            qf[kk][1] = f2tf32(qhi[c] * qscale);
            qf[kk][2] = f2tf32(qlo[c + 4] * qscale);
            qf[kk][3] = f2tf32(qhi[c + 4] * qscale);
        }
    }

    const float* kvbase = qkv + (size_t)(b * SS) * QKV_N + h * 192 + 64;
    auto load_tile = [&](int kt) {
        const int stage = kt & 1;
        const float* src = kvbase + (size_t)kt * 64 * QKV_N;
        const uint32_t kdst = sb + (stage * AT_KFL) * 4;
        const uint32_t vdst = sb + (AT_V0 + stage * AT_VFL) * 4;
#pragma unroll
        for (int it = 0; it < 4; it++) {
            int idx = it * 256 + tid;
            int row = idx >> 4;
            int c4  = (idx & 15) * 4;
            const float* g = src + (size_t)row * QKV_N + c4;
            asm volatile("cp.async.cg.shared.global [%0], [%1], 16;"
                         :: "r"(kdst + (uint32_t)(row * AT_KSTR + c4) * 4), "l"(g));
            asm volatile("cp.async.cg.shared.global [%0], [%1], 16;"
                         :: "r"(vdst + (uint32_t)(row * AT_VSTR + c4) * 4), "l"(g + 64));
        }
    };

    float m0 = -1e30f, m1 = -1e30f, l0 = 0.f, l1 = 0.f;
    float oacc[8][4];
#pragma unroll
    for (int nt = 0; nt < 8; nt++)
#pragma unroll
        for (int r = 0; r < 4; r++) oacc[nt][r] = 0.f;

    load_tile(0);
    asm volatile("cp.async.commit_group;" ::: "memory");

    const int NT = SS / 64;
    for (int kt = 0; kt < NT; kt++) {
        asm volatile("cp.async.wait_group 0;" ::: "memory");
        __syncthreads();
        if (kt + 1 < NT) {
            load_tile(kt + 1);
            asm volatile("cp.async.commit_group;" ::: "memory");
        }

        const int stage = kt & 1;
        const uint32_t* ks = k_sm + stage * AT_KFL;
        const uint32_t* vs = v_sm + stage * AT_VFL;

        float sacc[8][4];
#pragma unroll
        for (int nt = 0; nt < 8; nt++)
#pragma unroll
            for (int r = 0; r < 4; r++) sacc[nt][r] = 0.f;

#pragma unroll
        for (int kk = 0; kk < 8; kk++) {
            const int kb = kk * 8 + tig;
            uint32_t bfr[8][2];
#pragma unroll
            for (int nt = 0; nt < 8; nt++) {
                const int key = nt * 8 + gid;
                bfr[nt][0] = ks[key * AT_KSTR + kb];
                bfr[nt][1] = ks[key * AT_KSTR + kb + 4];
            }
#pragma unroll
            for (int nt = 0; nt < 8; nt++)
                mma_tf32(sacc[nt], qf[kk], bfr[nt]);
        }

        float tmax0 = -1e30f, tmax1 = -1e30f;
#pragma unroll
        for (int nt = 0; nt < 8; nt++) {
            tmax0 = fmaxf(tmax0, fmaxf(sacc[nt][0], sacc[nt][1]));
            tmax1 = fmaxf(tmax1, fmaxf(sacc[nt][2], sacc[nt][3]));
        }
        tmax0 = fmaxf(tmax0, __shfl_xor_sync(0xffffffffu, tmax0, 1));
        tmax0 = fmaxf(tmax0, __shfl_xor_sync(0xffffffffu, tmax0, 2));
        tmax1 = fmaxf(tmax1, __shfl_xor_sync(0xffffffffu, tmax1, 1));
        tmax1 = fmaxf(tmax1, __shfl_xor_sync(0xffffffffu, tmax1, 2));

        const float mn0 = fmaxf(m0, tmax0);
        const float mn1 = fmaxf(m1, tmax1);
        const float corr0 = ex2(m0 - mn0);
        const float corr1 = ex2(m1 - mn1);
        m0 = mn0; m1 = mn1;

        uint32_t pf[8][4];
        float sum0 = 0.f, sum1 = 0.f;
#pragma unroll
        for (int nt = 0; nt < 8; nt++) {
            float p0 = ex2(sacc[nt][0] - mn0);
            float p1 = ex2(sacc[nt][1] - mn0);
            float p2 = ex2(sacc[nt][2] - mn1);
            float p3 = ex2(sacc[nt][3] - mn1);
            sum0 += p0 + p1;
            sum1 += p2 + p3;
            pf[nt][0] = f2tf32(p0);
            pf[nt][1] = f2tf32(p2);
            pf[nt][2] = f2tf32(p1);
            pf[nt][3] = f2tf32(p3);
            oacc[nt][0] *= corr0;
            oacc[nt][1] *= corr0;
            oacc[nt][2] *= corr1;
            oacc[nt][3] *= corr1;
        }
        sum0 += __shfl_xor_sync(0xffffffffu, sum0, 1);
        sum0 += __shfl_xor_sync(0xffffffffu, sum0, 2);
        sum1 += __shfl_xor_sync(0xffffffffu, sum1, 1);
        sum1 += __shfl_xor_sync(0xffffffffu, sum1, 2);
        l0 = l0 * corr0 + sum0;
        l1 = l1 * corr1 + sum1;

#pragma unroll
        for (int kk = 0; kk < 8; kk++) {
            uint32_t bfr[8][2];
            const int r0 = (kk * 8 + 2 * tig) * AT_VSTR;
            const int r1 = r0 + AT_VSTR;
#pragma unroll
            for (int nt = 0; nt < 8; nt++) {
                const int d = nt * 8 + gid;
                bfr[nt][0] = vs[r0 + d];
                bfr[nt][1] = vs[r1 + d];
            }
#pragma unroll
            for (int nt = 0; nt < 8; nt++)
                mma_tf32(oacc[nt], pf[kk], bfr[nt]);
        }
    }

    const float inv0 = 1.f / l0;
    const float inv1 = 1.f / l1;
    float* olo = vals + (size_t)(b * SS + q0 + wid * 16 + gid) * DD + h * HDIM;
    float* ohi = olo + 8 * DD;
#pragma unroll
    for (int nt = 0; nt < 8; nt++) {
        const int c = nt * 8 + 2 * tig;
        float2 r0, r1;
        r0.x = oacc[nt][0] * inv0;
        r0.y = oacc[nt][1] * inv0;
        r1.x = oacc[nt][2] * inv1;
        r1.y = oacc[nt][3] * inv1;
        *(float2*)(olo + c) = r0;
        *(float2*)(ohi + c) = r1;
    }
}

// ---------------------------------------------------------------------------
// Launch
// ---------------------------------------------------------------------------
extern "C" void kernel_launch(void* const* d_in, const int* in_sizes, int n_in,
                              void* d_out, int out_size)
{
    const float* x      = (const float*)d_in[0];
    const float* w_qkv  = (const float*)d_in[1];
    const float* b_qkv  = (const float*)d_in[2];
    const float* w_o    = (const float*)d_in[3];
    const float* b_o    = (const float*)d_in[4];
    float* out = (float*)d_out;

    float *qkv_buf, *vals_buf, *xc, *valsp, *wqc, *woc;
    cudaGetSymbolAddress((void**)&qkv_buf, g_qkv);
    cudaGetSymbolAddress((void**)&vals_buf, g_vals);
    cudaGetSymbolAddress((void**)&xc,    g_xc);
    cudaGetSymbolAddress((void**)&valsp, g_valsp);
    cudaGetSymbolAddress((void**)&wqc,   g_wqc);
    cudaGetSymbolAddress((void**)&woc,   g_woc);

    cudaFuncSetAttribute(gemm_mma_kernel,
                         cudaFuncAttributeMaxDynamicSharedMemorySize,
                         GEMM_SMEM_BYTES);
    cudaFuncSetAttribute(attn_mma_kernel,
                         cudaFuncAttributeMaxDynamicSharedMemorySize,
                         ATT_SMEM_BYTES);

    // 0) fragment-pack inputs (with tf32 rounding)
    pack_a_kernel<<<(M_ROWS / 128) * (DIN / 32), 256>>>(x, xc, DIN);
    pack_b_kernel<<<(QKV_N / 128) * (DIN / 32), 256>>>(w_qkv, wqc, DIN);
    pack_b_kernel<<<(DD / 128) * (DIN / 32), 256>>>(w_o, woc, DIN);

    // 1) QKV projection -> g_qkv (row-major, tf32-rounded)
    {
        dim3 grid(QKV_N / 128, M_ROWS / 128);
        gemm_mma_kernel<<<grid, 256, GEMM_SMEM_BYTES>>>(
            xc, wqc, b_qkv, qkv_buf, M_ROWS, QKV_N, DIN, 1);
    }

    // 2) Attention -> g_vals (row-major)
    {
        dim3 grid(SS / 128, HH, BB);
        attn_mma_kernel<<<grid, 256, ATT_SMEM_BYTES>>>(qkv_buf, vals_buf);
    }

    // 3) pack attention output, then O-projection -> out
    pack_a_kernel<<<(M_ROWS / 128) * (DD / 32), 256>>>(vals_buf, valsp, DD);
    {
        dim3 grid(DD / 128, M_ROWS / 128);
        gemm_mma_kernel<<<grid, 256, GEMM_SMEM_BYTES>>>(
            valsp, woc, b_o, out, M_ROWS, DD, DIN, 0);
    }
}

// round 8
// speedup vs baseline: 5.3390x; 1.0528x over previous
#include <cuda_runtime.h>
#include <cuda_bf16.h>
#include <cstdint>
#include <math.h>

// Problem constants
#define BB   2
#define SS   2048
#define DIN  1024
#define DD   1024
#define HH   16
#define HDIM 64
#define M_ROWS (BB * SS)      // 4096
#define QKV_N  (3 * DD)       // 3072

// Scratch
__device__ float g_qkv  [M_ROWS * QKV_N];     // qkv row-major, tf32-rounded
__device__ float g_vals [M_ROWS * DD];        // attention out, row-major
__device__ float g_xc   [M_ROWS * DIN];       // x, fragment-packed
__device__ float g_valsp[M_ROWS * DD];        // vals, fragment-packed
__device__ float g_wqc  [QKV_N * DIN];        // w_qkv, fragment-packed
__device__ float g_woc  [DD * DD];            // w_o, fragment-packed
__device__ float g_kvp  [BB * HH * 32 * 8192]; // K/V fragment-packed per tile

// ---------------------------------------------------------------------------
// Helpers
// ---------------------------------------------------------------------------
__device__ __forceinline__ uint32_t smem_u32(const void* p) {
    uint32_t a;
    asm("{ .reg .u64 t; cvta.to.shared.u64 t, %1; cvt.u32.u64 %0, t; }"
        : "=r"(a) : "l"(p));
    return a;
}

__device__ __forceinline__ uint32_t f2tf32(float f) {
    uint32_t u;
    asm("cvt.rna.tf32.f32 %0, %1;" : "=r"(u) : "f"(f));
    return u;
}

__device__ __forceinline__ float ex2(float x) {
    float r;
    asm("ex2.approx.f32 %0, %1;" : "=f"(r) : "f"(x));
    return r;
}

__device__ __forceinline__ void mma_tf32(float* d, const uint32_t* a, const uint32_t* b) {
    asm("mma.sync.aligned.m16n8k8.row.col.f32.tf32.tf32.f32 "
        "{%0,%1,%2,%3}, {%4,%5,%6,%7}, {%8,%9}, {%0,%1,%2,%3};"
        : "+f"(d[0]), "+f"(d[1]), "+f"(d[2]), "+f"(d[3])
        : "r"(a[0]), "r"(a[1]), "r"(a[2]), "r"(a[3]),
          "r"(b[0]), "r"(b[1]));
}

// ---------------------------------------------------------------------------
// Fragment repack kernels for GEMM operands (unchanged from round 7).
// ---------------------------------------------------------------------------
__global__ __launch_bounds__(256) void pack_a_kernel(
    const float* __restrict__ src, float* __restrict__ dst, int K)
{
    __shared__ float sm[128 * 33];
    const int tid = threadIdx.x;
    const int kt  = blockIdx.x % (K / 32);
    const int mt  = blockIdx.x / (K / 32);
    const float* g = src + (size_t)(mt * 128) * K + kt * 32;
#pragma unroll
    for (int it = 0; it < 4; it++) {
        int idx = it * 256 + tid;
        int r = idx >> 3;
        int c4 = (idx & 7) * 4;
        float4 v = *(const float4*)(g + (size_t)r * K + c4);
        sm[r * 33 + c4 + 0] = __uint_as_float(f2tf32(v.x));
        sm[r * 33 + c4 + 1] = __uint_as_float(f2tf32(v.y));
        sm[r * 33 + c4 + 2] = __uint_as_float(f2tf32(v.z));
        sm[r * 33 + c4 + 3] = __uint_as_float(f2tf32(v.w));
    }
    __syncthreads();
    float4* o = (float4*)(dst + (size_t)blockIdx.x * 4096);
#pragma unroll
    for (int it = 0; it < 4; it++) {
        int q = it * 256 + tid;
        int grp = q >> 7;
        int kk = (q >> 5) & 3;
        int lane = q & 31;
        int gid = lane >> 2;
        int tig = lane & 3;
        int r0 = (grp >> 2) * 64 + (grp & 3) * 16 + gid;
        int kb = kk * 8 + tig;
        float4 w;
        w.x = sm[r0 * 33 + kb];
        w.y = sm[(r0 + 8) * 33 + kb];
        w.z = sm[r0 * 33 + kb + 4];
        w.w = sm[(r0 + 8) * 33 + kb + 4];
        o[q] = w;
    }
}

__global__ __launch_bounds__(256) void pack_b_kernel(
    const float* __restrict__ src, float* __restrict__ dst, int K)
{
    __shared__ float sm[128 * 33];
    const int tid = threadIdx.x;
    const int kt  = blockIdx.x % (K / 32);
    const int nt  = blockIdx.x / (K / 32);
    const float* g = src + (size_t)(nt * 128) * K + kt * 32;
#pragma unroll
    for (int it = 0; it < 4; it++) {
        int idx = it * 256 + tid;
        int r = idx >> 3;
        int c4 = (idx & 7) * 4;
        float4 v = *(const float4*)(g + (size_t)r * K + c4);
        sm[r * 33 + c4 + 0] = __uint_as_float(f2tf32(v.x));
        sm[r * 33 + c4 + 1] = __uint_as_float(f2tf32(v.y));
        sm[r * 33 + c4 + 2] = __uint_as_float(f2tf32(v.z));
        sm[r * 33 + c4 + 3] = __uint_as_float(f2tf32(v.w));
    }
    __syncthreads();
    float2* o = (float2*)(dst + (size_t)blockIdx.x * 4096);
#pragma unroll
    for (int it = 0; it < 8; it++) {
        int q = it * 256 + tid;
        int grp = q >> 7;
        int kk = (q >> 5) & 3;
        int lane = q & 31;
        int n = grp * 8 + (lane >> 2);
        int kb = kk * 8 + (lane & 3);
        float2 w;
        w.x = sm[n * 33 + kb];
        w.y = sm[n * 33 + kb + 4];
        o[q] = w;
    }
}

// ---------------------------------------------------------------------------
// K/V fragment pack for attention.  One block = one (b, h, 64-key tile).
// Output tile (8192 floats): [K-pack 4096][V-pack 4096].
//  K chunk (float2) at ((kk*8+nt)*32+lane):
//     { K[nt*8+gid][kk*8+tig], K[nt*8+gid][kk*8+tig+4] }
//  V chunk (float2) at ((kk*8+nt)*32+lane):
//     { V[kk*8+2*tig][nt*8+gid], V[kk*8+2*tig+1][nt*8+gid] }
//  (gid=lane>>2, tig=lane&3; values identical to the round-7 gathers)
// ---------------------------------------------------------------------------
#define PKV_STR 68
__global__ __launch_bounds__(256) void pack_kv_kernel(
    const float* __restrict__ qkv, float* __restrict__ kvp)
{
    __shared__ float ksm[64 * PKV_STR];
    __shared__ float vsm[64 * PKV_STR];
    const int tid = threadIdx.x;
    const int kt = blockIdx.x;
    const int h  = blockIdx.y;
    const int b  = blockIdx.z;

    const float* src = qkv + (size_t)(b * SS + kt * 64) * QKV_N + h * 192 + 64;
#pragma unroll
    for (int it = 0; it < 4; it++) {
        int idx = it * 256 + tid;
        int row = idx >> 4;
        int c4  = (idx & 15) * 4;
        const float* g = src + (size_t)row * QKV_N + c4;
        *(float4*)&ksm[row * PKV_STR + c4] = *(const float4*)g;
        *(float4*)&vsm[row * PKV_STR + c4] = *(const float4*)(g + 64);
    }
    __syncthreads();

    float2* ko = (float2*)(kvp + (size_t)((b * HH + h) * 32 + kt) * 8192);
    float2* vo = ko + 2048;
#pragma unroll
    for (int it = 0; it < 8; it++) {
        int q = it * 256 + tid;          // 0..2047
        int kk = q >> 8;                 // 0..7
        int nt = (q >> 5) & 7;           // 0..7
        int lane = q & 31;
        int gid = lane >> 2;
        int tig = lane & 3;
        float2 kw;
        kw.x = ksm[(nt * 8 + gid) * PKV_STR + kk * 8 + tig];
        kw.y = ksm[(nt * 8 + gid) * PKV_STR + kk * 8 + tig + 4];
        ko[q] = kw;
        float2 vw;
        vw.x = vsm[(kk * 8 + 2 * tig) * PKV_STR + nt * 8 + gid];
        vw.y = vsm[(kk * 8 + 2 * tig + 1) * PKV_STR + nt * 8 + gid];
        vo[q] = vw;
    }
}

// ---------------------------------------------------------------------------
// mma.sync tf32 GEMM on fragment-packed operands (unchanged from round 7).
// ---------------------------------------------------------------------------
#define TILE_FL     4096
#define GM_STAGES   3
#define GEMM_SMEM_BYTES (2 * GM_STAGES * TILE_FL * 4)   // 98304

__global__ __launch_bounds__(256, 2) void gemm_mma_kernel(
    const float* __restrict__ A, const float* __restrict__ Bw,
    const float* __restrict__ bias, float* __restrict__ C,
    int M, int N, int K, int cvt_out)
{
    extern __shared__ float smf[];
    const uint32_t sb = smem_u32(smf);
    const int tid  = threadIdx.x;
    const int wid  = tid >> 5;
    const int lane = tid & 31;
    const int gid  = lane >> 2;
    const int tig  = lane & 3;
    const int wm2  = wid >> 2;
    const int wgrp = wid & 3;
    const int m0 = blockIdx.y * 128;
    const int n0 = blockIdx.x * 128;
    const int KT = K / 32;

    float acc[4][4][4];
#pragma unroll
    for (int i = 0; i < 4; i++)
#pragma unroll
        for (int j = 0; j < 4; j++)
#pragma unroll
            for (int r = 0; r < 4; r++) acc[i][j][r] = 0.f;

    auto load_stage = [&](int chunk, int stage) {
        const float* ag = A + ((size_t)blockIdx.y * KT + chunk) * TILE_FL;
        const float* bg = Bw + ((size_t)blockIdx.x * KT + chunk) * TILE_FL;
        const uint32_t a_s = sb + stage * (TILE_FL * 4);
        const uint32_t b_s = sb + (GM_STAGES + stage) * (TILE_FL * 4);
#pragma unroll
        for (int it = 0; it < 4; it++) {
            int idx = it * 256 + tid;
            asm volatile("cp.async.cg.shared.global [%0], [%1], 16;"
                         :: "r"(a_s + idx * 16), "l"(ag + idx * 4));
            asm volatile("cp.async.cg.shared.global [%0], [%1], 16;"
                         :: "r"(b_s + idx * 16), "l"(bg + idx * 4));
        }
    };

    load_stage(0, 0);
    asm volatile("cp.async.commit_group;" ::: "memory");
    load_stage(1, 1);
    asm volatile("cp.async.commit_group;" ::: "memory");

    int cstage = 0;
    int lstage = 2;
    for (int j = 0; j < KT; j++) {
        if (j + 1 < KT) {
            asm volatile("cp.async.wait_group 1;" ::: "memory");
        } else {
            asm volatile("cp.async.wait_group 0;" ::: "memory");
        }
        __syncthreads();
        if (j + 2 < KT) {
            load_stage(j + 2, lstage);
            asm volatile("cp.async.commit_group;" ::: "memory");
        }

        const float4* at4 = (const float4*)(smf + cstage * TILE_FL);
        const float2* bt2 = (const float2*)(smf + (GM_STAGES + cstage) * TILE_FL);

#pragma unroll
        for (int kk = 0; kk < 4; kk++) {
            float4 afr[4];
#pragma unroll
            for (int mt = 0; mt < 4; mt++)
                afr[mt] = at4[(((wm2 * 4 + mt) * 4 + kk) << 5) + lane];
            float2 bfr[4];
#pragma unroll
            for (int nt = 0; nt < 4; nt++)
                bfr[nt] = bt2[(((wgrp * 4 + nt) * 4 + kk) << 5) + lane];
#pragma unroll
            for (int mt = 0; mt < 4; mt++)
#pragma unroll
                for (int nt = 0; nt < 4; nt++)
                    mma_tf32(acc[mt][nt],
                             (const uint32_t*)&afr[mt],
                             (const uint32_t*)&bfr[nt]);
        }
        cstage = (cstage == GM_STAGES - 1) ? 0 : cstage + 1;
        lstage = (lstage == GM_STAGES - 1) ? 0 : lstage + 1;
    }

#pragma unroll
    for (int mt = 0; mt < 4; mt++) {
        const int row = m0 + wm2 * 64 + mt * 16 + gid;
#pragma unroll
        for (int nt = 0; nt < 4; nt++) {
            const int col = n0 + wgrp * 32 + nt * 8 + tig * 2;
            float2 bv = *(const float2*)(bias + col);
            float2 o0, o1;
            o0.x = acc[mt][nt][0] + bv.x;
            o0.y = acc[mt][nt][1] + bv.y;
            o1.x = acc[mt][nt][2] + bv.x;
            o1.y = acc[mt][nt][3] + bv.y;
            if (cvt_out) {
                o0.x = __uint_as_float(f2tf32(o0.x));
                o0.y = __uint_as_float(f2tf32(o0.y));
                o1.x = __uint_as_float(f2tf32(o1.x));
                o1.y = __uint_as_float(f2tf32(o1.y));
            }
            *(float2*)(C + (size_t)row * N + col) = o0;
            *(float2*)(C + (size_t)(row + 8) * N + col) = o1;
        }
    }
}

// ---------------------------------------------------------------------------
// Flash attention on fragment-packed K/V.
// SMEM: 2 stages x 32KB (K-pack + V-pack) = 64KB -> 2 CTAs/SM.
// All fragment loads: contiguous LDS.64, conflict-free.
// ---------------------------------------------------------------------------
#define ATP_ST_FL 8192
#define ATT_SMEM_BYTES (2 * ATP_ST_FL * 4)   // 65536

__global__ __launch_bounds__(256, 2) void attn_mma_kernel(
    const float* __restrict__ qkv, const float* __restrict__ kvp,
    float* __restrict__ vals)
{
    extern __shared__ float fsm[];
    const uint32_t sb = smem_u32(fsm);

    const int tid  = threadIdx.x;
    const int wid  = tid >> 5;
    const int lane = tid & 31;
    const int gid  = lane >> 2;
    const int tig  = lane & 3;
    const int b  = blockIdx.z;
    const int h  = blockIdx.y;
    const int q0 = blockIdx.x * 128;

    const float qscale = 0.125f * 1.4426950408889634f;

    uint32_t qf[8][4];
    {
        const float* qlo = qkv + (size_t)(b * SS + q0 + wid * 16 + gid) * QKV_N + h * 192;
        const float* qhi = qlo + 8 * QKV_N;
#pragma unroll
        for (int kk = 0; kk < 8; kk++) {
            const int c = kk * 8 + tig;
            qf[kk][0] = f2tf32(qlo[c] * qscale);
            qf[kk][1] = f2tf32(qhi[c] * qscale);
            qf[kk][2] = f2tf32(qlo[c + 4] * qscale);
            qf[kk][3] = f2tf32(qhi[c + 4] * qscale);
        }
    }

    const float* kvbase = kvp + (size_t)(b * HH + h) * 32 * ATP_ST_FL;
    auto load_tile = [&](int kt) {
        const int stage = kt & 1;
        const float* src = kvbase + (size_t)kt * ATP_ST_FL;
        const uint32_t dst = sb + stage * (ATP_ST_FL * 4);
#pragma unroll
        for (int it = 0; it < 8; it++) {
            int idx = it * 256 + tid;
            asm volatile("cp.async.cg.shared.global [%0], [%1], 16;"
                         :: "r"(dst + idx * 16), "l"(src + idx * 4));
        }
    };

    float m0 = -1e30f, m1 = -1e30f, l0 = 0.f, l1 = 0.f;
    float oacc[8][4];
#pragma unroll
    for (int nt = 0; nt < 8; nt++)
#pragma unroll
        for (int r = 0; r < 4; r++) oacc[nt][r] = 0.f;

    load_tile(0);
    asm volatile("cp.async.commit_group;" ::: "memory");

    const int NT = SS / 64;
    for (int kt = 0; kt < NT; kt++) {
        asm volatile("cp.async.wait_group 0;" ::: "memory");
        __syncthreads();
        if (kt + 1 < NT) {
            load_tile(kt + 1);
            asm volatile("cp.async.commit_group;" ::: "memory");
        }

        const int stage = kt & 1;
        const float2* kp2 = (const float2*)(fsm + stage * ATP_ST_FL);
        const float2* vp2 = kp2 + 2048;

        // ---- S = Q @ K^T ----
        float sacc[8][4];
#pragma unroll
        for (int nt = 0; nt < 8; nt++)
#pragma unroll
            for (int r = 0; r < 4; r++) sacc[nt][r] = 0.f;

#pragma unroll
        for (int kk = 0; kk < 8; kk++) {
            float2 bfr[8];
#pragma unroll
            for (int nt = 0; nt < 8; nt++)
                bfr[nt] = kp2[((kk * 8 + nt) << 5) + lane];
#pragma unroll
            for (int nt = 0; nt < 8; nt++)
                mma_tf32(sacc[nt], qf[kk], (const uint32_t*)&bfr[nt]);
        }

        // ---- online softmax (log2 domain) ----
        float tmax0 = -1e30f, tmax1 = -1e30f;
#pragma unroll
        for (int nt = 0; nt < 8; nt++) {
            tmax0 = fmaxf(tmax0, fmaxf(sacc[nt][0], sacc[nt][1]));
            tmax1 = fmaxf(tmax1, fmaxf(sacc[nt][2], sacc[nt][3]));
        }
        tmax0 = fmaxf(tmax0, __shfl_xor_sync(0xffffffffu, tmax0, 1));
        tmax0 = fmaxf(tmax0, __shfl_xor_sync(0xffffffffu, tmax0, 2));
        tmax1 = fmaxf(tmax1, __shfl_xor_sync(0xffffffffu, tmax1, 1));
        tmax1 = fmaxf(tmax1, __shfl_xor_sync(0xffffffffu, tmax1, 2));

        const float mn0 = fmaxf(m0, tmax0);
        const float mn1 = fmaxf(m1, tmax1);
        const float corr0 = ex2(m0 - mn0);
        const float corr1 = ex2(m1 - mn1);
        m0 = mn0; m1 = mn1;

        uint32_t pf[8][4];
        float sum0 = 0.f, sum1 = 0.f;
#pragma unroll
        for (int nt = 0; nt < 8; nt++) {
            float p0 = ex2(sacc[nt][0] - mn0);
            float p1 = ex2(sacc[nt][1] - mn0);
            float p2 = ex2(sacc[nt][2] - mn1);
            float p3 = ex2(sacc[nt][3] - mn1);
            sum0 += p0 + p1;
            sum1 += p2 + p3;
            pf[nt][0] = f2tf32(p0);
            pf[nt][1] = f2tf32(p2);
            pf[nt][2] = f2tf32(p1);
            pf[nt][3] = f2tf32(p3);
            oacc[nt][0] *= corr0;
            oacc[nt][1] *= corr0;
            oacc[nt][2] *= corr1;
            oacc[nt][3] *= corr1;
        }
        sum0 += __shfl_xor_sync(0xffffffffu, sum0, 1);
        sum0 += __shfl_xor_sync(0xffffffffu, sum0, 2);
        sum1 += __shfl_xor_sync(0xffffffffu, sum1, 1);
        sum1 += __shfl_xor_sync(0xffffffffu, sum1, 2);
        l0 = l0 * corr0 + sum0;
        l1 = l1 * corr1 + sum1;

        // ---- O += P @ V (packed V already in permuted fragment order) ----
#pragma unroll
        for (int kk = 0; kk < 8; kk++) {
            float2 bfr[8];
#pragma unroll
            for (int nt = 0; nt < 8; nt++)
                bfr[nt] = vp2[((kk * 8 + nt) << 5) + lane];
#pragma unroll
            for (int nt = 0; nt < 8; nt++)
                mma_tf32(oacc[nt], pf[kk], (const uint32_t*)&bfr[nt]);
        }
    }

    const float inv0 = 1.f / l0;
    const float inv1 = 1.f / l1;
    float* olo = vals + (size_t)(b * SS + q0 + wid * 16 + gid) * DD + h * HDIM;
    float* ohi = olo + 8 * DD;
#pragma unroll
    for (int nt = 0; nt < 8; nt++) {
        const int c = nt * 8 + 2 * tig;
        float2 r0, r1;
        r0.x = oacc[nt][0] * inv0;
        r0.y = oacc[nt][1] * inv0;
        r1.x = oacc[nt][2] * inv1;
        r1.y = oacc[nt][3] * inv1;
        *(float2*)(olo + c) = r0;
        *(float2*)(ohi + c) = r1;
    }
}

// ---------------------------------------------------------------------------
// Launch
// ---------------------------------------------------------------------------
extern "C" void kernel_launch(void* const* d_in, const int* in_sizes, int n_in,
                              void* d_out, int out_size)
{
    const float* x      = (const float*)d_in[0];
    const float* w_qkv  = (const float*)d_in[1];
    const float* b_qkv  = (const float*)d_in[2];
    const float* w_o    = (const float*)d_in[3];
    const float* b_o    = (const float*)d_in[4];
    float* out = (float*)d_out;

    float *qkv_buf, *vals_buf, *xc, *valsp, *wqc, *woc, *kvp;
    cudaGetSymbolAddress((void**)&qkv_buf, g_qkv);
    cudaGetSymbolAddress((void**)&vals_buf, g_vals);
    cudaGetSymbolAddress((void**)&xc,    g_xc);
    cudaGetSymbolAddress((void**)&valsp, g_valsp);
    cudaGetSymbolAddress((void**)&wqc,   g_wqc);
    cudaGetSymbolAddress((void**)&woc,   g_woc);
    cudaGetSymbolAddress((void**)&kvp,   g_kvp);

    cudaFuncSetAttribute(gemm_mma_kernel,
                         cudaFuncAttributeMaxDynamicSharedMemorySize,
                         GEMM_SMEM_BYTES);
    cudaFuncSetAttribute(attn_mma_kernel,
                         cudaFuncAttributeMaxDynamicSharedMemorySize,
                         ATT_SMEM_BYTES);

    // 0) fragment-pack GEMM inputs (with tf32 rounding)
    pack_a_kernel<<<(M_ROWS / 128) * (DIN / 32), 256>>>(x, xc, DIN);
    pack_b_kernel<<<(QKV_N / 128) * (DIN / 32), 256>>>(w_qkv, wqc, DIN);
    pack_b_kernel<<<(DD / 128) * (DIN / 32), 256>>>(w_o, woc, DIN);

    // 1) QKV projection -> g_qkv (row-major, tf32-rounded)
    {
        dim3 grid(QKV_N / 128, M_ROWS / 128);
        gemm_mma_kernel<<<grid, 256, GEMM_SMEM_BYTES>>>(
            xc, wqc, b_qkv, qkv_buf, M_ROWS, QKV_N, DIN, 1);
    }

    // 1b) fragment-pack K/V tiles
    {
        dim3 grid(SS / 64, HH, BB);
        pack_kv_kernel<<<grid, 256>>>(qkv_buf, kvp);
    }

    // 2) Attention -> g_vals (row-major)
    {
        dim3 grid(SS / 128, HH, BB);
        attn_mma_kernel<<<grid, 256, ATT_SMEM_BYTES>>>(qkv_buf, kvp, vals_buf);
    }

    // 3) pack attention output, then O-projection -> out
    pack_a_kernel<<<(M_ROWS / 128) * (DD / 32), 256>>>(vals_buf, valsp, DD);
    {
        dim3 grid(DD / 128, M_ROWS / 128);
        gemm_mma_kernel<<<grid, 256, GEMM_SMEM_BYTES>>>(
            valsp, woc, b_o, out, M_ROWS, DD, DIN, 0);
    }
}

// round 9
// speedup vs baseline: 5.3995x; 1.0113x over previous
#include <cuda_runtime.h>
#include <cuda_bf16.h>
#include <cstdint>
#include <math.h>

// Problem constants
#define BB   2
#define SS   2048
#define DIN  1024
#define DD   1024
#define HH   16
#define HDIM 64
#define M_ROWS (BB * SS)      // 4096
#define QKV_N  (3 * DD)       // 3072

// Scratch
__device__ float g_qkv  [M_ROWS * QKV_N];
__device__ float g_vals [M_ROWS * DD];
__device__ float g_xc   [M_ROWS * DIN];
__device__ float g_valsp[M_ROWS * DD];
__device__ float g_wqc  [QKV_N * DIN];
__device__ float g_woc  [DD * DD];
__device__ float g_kvp  [BB * HH * 32 * 8192];

// ---------------------------------------------------------------------------
// Helpers
// ---------------------------------------------------------------------------
__device__ __forceinline__ uint32_t smem_u32(const void* p) {
    uint32_t a;
    asm("{ .reg .u64 t; cvta.to.shared.u64 t, %1; cvt.u32.u64 %0, t; }"
        : "=r"(a) : "l"(p));
    return a;
}

__device__ __forceinline__ uint32_t f2tf32(float f) {
    uint32_t u;
    asm("cvt.rna.tf32.f32 %0, %1;" : "=r"(u) : "f"(f));
    return u;
}

__device__ __forceinline__ float ex2(float x) {
    float r;
    asm("ex2.approx.f32 %0, %1;" : "=f"(r) : "f"(x));
    return r;
}

__device__ __forceinline__ void mma_tf32(float* d, const uint32_t* a, const uint32_t* b) {
    asm("mma.sync.aligned.m16n8k8.row.col.f32.tf32.tf32.f32 "
        "{%0,%1,%2,%3}, {%4,%5,%6,%7}, {%8,%9}, {%0,%1,%2,%3};"
        : "+f"(d[0]), "+f"(d[1]), "+f"(d[2]), "+f"(d[3])
        : "r"(a[0]), "r"(a[1]), "r"(a[2]), "r"(a[3]),
          "r"(b[0]), "r"(b[1]));
}

// ---------------------------------------------------------------------------
// Fragment repack kernels for GEMM operands (unchanged).
// ---------------------------------------------------------------------------
__global__ __launch_bounds__(256) void pack_a_kernel(
    const float* __restrict__ src, float* __restrict__ dst, int K)
{
    __shared__ float sm[128 * 33];
    const int tid = threadIdx.x;
    const int kt  = blockIdx.x % (K / 32);
    const int mt  = blockIdx.x / (K / 32);
    const float* g = src + (size_t)(mt * 128) * K + kt * 32;
#pragma unroll
    for (int it = 0; it < 4; it++) {
        int idx = it * 256 + tid;
        int r = idx >> 3;
        int c4 = (idx & 7) * 4;
        float4 v = *(const float4*)(g + (size_t)r * K + c4);
        sm[r * 33 + c4 + 0] = __uint_as_float(f2tf32(v.x));
        sm[r * 33 + c4 + 1] = __uint_as_float(f2tf32(v.y));
        sm[r * 33 + c4 + 2] = __uint_as_float(f2tf32(v.z));
        sm[r * 33 + c4 + 3] = __uint_as_float(f2tf32(v.w));
    }
    __syncthreads();
    float4* o = (float4*)(dst + (size_t)blockIdx.x * 4096);
#pragma unroll
    for (int it = 0; it < 4; it++) {
        int q = it * 256 + tid;
        int grp = q >> 7;
        int kk = (q >> 5) & 3;
        int lane = q & 31;
        int gid = lane >> 2;
        int tig = lane & 3;
        int r0 = (grp >> 2) * 64 + (grp & 3) * 16 + gid;
        int kb = kk * 8 + tig;
        float4 w;
        w.x = sm[r0 * 33 + kb];
        w.y = sm[(r0 + 8) * 33 + kb];
        w.z = sm[r0 * 33 + kb + 4];
        w.w = sm[(r0 + 8) * 33 + kb + 4];
        o[q] = w;
    }
}

__global__ __launch_bounds__(256) void pack_b_kernel(
    const float* __restrict__ src, float* __restrict__ dst, int K)
{
    __shared__ float sm[128 * 33];
    const int tid = threadIdx.x;
    const int kt  = blockIdx.x % (K / 32);
    const int nt  = blockIdx.x / (K / 32);
    const float* g = src + (size_t)(nt * 128) * K + kt * 32;
#pragma unroll
    for (int it = 0; it < 4; it++) {
        int idx = it * 256 + tid;
        int r = idx >> 3;
        int c4 = (idx & 7) * 4;
        float4 v = *(const float4*)(g + (size_t)r * K + c4);
        sm[r * 33 + c4 + 0] = __uint_as_float(f2tf32(v.x));
        sm[r * 33 + c4 + 1] = __uint_as_float(f2tf32(v.y));
        sm[r * 33 + c4 + 2] = __uint_as_float(f2tf32(v.z));
        sm[r * 33 + c4 + 3] = __uint_as_float(f2tf32(v.w));
    }
    __syncthreads();
    float2* o = (float2*)(dst + (size_t)blockIdx.x * 4096);
#pragma unroll
    for (int it = 0; it < 8; it++) {
        int q = it * 256 + tid;
        int grp = q >> 7;
        int kk = (q >> 5) & 3;
        int lane = q & 31;
        int n = grp * 8 + (lane >> 2);
        int kb = kk * 8 + (lane & 3);
        float2 w;
        w.x = sm[n * 33 + kb];
        w.y = sm[n * 33 + kb + 4];
        o[q] = w;
    }
}

// ---------------------------------------------------------------------------
// K/V fragment pack for attention (unchanged from round 8).
// ---------------------------------------------------------------------------
#define PKV_STR 68
__global__ __launch_bounds__(256) void pack_kv_kernel(
    const float* __restrict__ qkv, float* __restrict__ kvp)
{
    __shared__ float ksm[64 * PKV_STR];
    __shared__ float vsm[64 * PKV_STR];
    const int tid = threadIdx.x;
    const int kt = blockIdx.x;
    const int h  = blockIdx.y;
    const int b  = blockIdx.z;

    const float* src = qkv + (size_t)(b * SS + kt * 64) * QKV_N + h * 192 + 64;
#pragma unroll
    for (int it = 0; it < 4; it++) {
        int idx = it * 256 + tid;
        int row = idx >> 4;
        int c4  = (idx & 15) * 4;
        const float* g = src + (size_t)row * QKV_N + c4;
        *(float4*)&ksm[row * PKV_STR + c4] = *(const float4*)g;
        *(float4*)&vsm[row * PKV_STR + c4] = *(const float4*)(g + 64);
    }
    __syncthreads();

    float2* ko = (float2*)(kvp + (size_t)((b * HH + h) * 32 + kt) * 8192);
    float2* vo = ko + 2048;
#pragma unroll
    for (int it = 0; it < 8; it++) {
        int q = it * 256 + tid;
        int kk = q >> 8;
        int nt = (q >> 5) & 7;
        int lane = q & 31;
        int gid = lane >> 2;
        int tig = lane & 3;
        float2 kw;
        kw.x = ksm[(nt * 8 + gid) * PKV_STR + kk * 8 + tig];
        kw.y = ksm[(nt * 8 + gid) * PKV_STR + kk * 8 + tig + 4];
        ko[q] = kw;
        float2 vw;
        vw.x = vsm[(kk * 8 + 2 * tig) * PKV_STR + nt * 8 + gid];
        vw.y = vsm[(kk * 8 + 2 * tig + 1) * PKV_STR + nt * 8 + gid];
        vo[q] = vw;
    }
}

// ---------------------------------------------------------------------------
// mma.sync tf32 GEMM on fragment-packed operands (unchanged).
// ---------------------------------------------------------------------------
#define TILE_FL     4096
#define GM_STAGES   3
#define GEMM_SMEM_BYTES (2 * GM_STAGES * TILE_FL * 4)

__global__ __launch_bounds__(256, 2) void gemm_mma_kernel(
    const float* __restrict__ A, const float* __restrict__ Bw,
    const float* __restrict__ bias, float* __restrict__ C,
    int M, int N, int K, int cvt_out)
{
    extern __shared__ float smf[];
    const uint32_t sb = smem_u32(smf);
    const int tid  = threadIdx.x;
    const int wid  = tid >> 5;
    const int lane = tid & 31;
    const int gid  = lane >> 2;
    const int tig  = lane & 3;
    const int wm2  = wid >> 2;
    const int wgrp = wid & 3;
    const int m0 = blockIdx.y * 128;
    const int n0 = blockIdx.x * 128;
    const int KT = K / 32;

    float acc[4][4][4];
#pragma unroll
    for (int i = 0; i < 4; i++)
#pragma unroll
        for (int j = 0; j < 4; j++)
#pragma unroll
            for (int r = 0; r < 4; r++) acc[i][j][r] = 0.f;

    auto load_stage = [&](int chunk, int stage) {
        const float* ag = A + ((size_t)blockIdx.y * KT + chunk) * TILE_FL;
        const float* bg = Bw + ((size_t)blockIdx.x * KT + chunk) * TILE_FL;
        const uint32_t a_s = sb + stage * (TILE_FL * 4);
        const uint32_t b_s = sb + (GM_STAGES + stage) * (TILE_FL * 4);
#pragma unroll
        for (int it = 0; it < 4; it++) {
            int idx = it * 256 + tid;
            asm volatile("cp.async.cg.shared.global [%0], [%1], 16;"
                         :: "r"(a_s + idx * 16), "l"(ag + idx * 4));
            asm volatile("cp.async.cg.shared.global [%0], [%1], 16;"
                         :: "r"(b_s + idx * 16), "l"(bg + idx * 4));
        }
    };

    load_stage(0, 0);
    asm volatile("cp.async.commit_group;" ::: "memory");
    load_stage(1, 1);
    asm volatile("cp.async.commit_group;" ::: "memory");

    int cstage = 0;
    int lstage = 2;
    for (int j = 0; j < KT; j++) {
        if (j + 1 < KT) {
            asm volatile("cp.async.wait_group 1;" ::: "memory");
        } else {
            asm volatile("cp.async.wait_group 0;" ::: "memory");
        }
        __syncthreads();
        if (j + 2 < KT) {
            load_stage(j + 2, lstage);
            asm volatile("cp.async.commit_group;" ::: "memory");
        }

        const float4* at4 = (const float4*)(smf + cstage * TILE_FL);
        const float2* bt2 = (const float2*)(smf + (GM_STAGES + cstage) * TILE_FL);

#pragma unroll
        for (int kk = 0; kk < 4; kk++) {
            float4 afr[4];
#pragma unroll
            for (int mt = 0; mt < 4; mt++)
                afr[mt] = at4[(((wm2 * 4 + mt) * 4 + kk) << 5) + lane];
            float2 bfr[4];
#pragma unroll
            for (int nt = 0; nt < 4; nt++)
                bfr[nt] = bt2[(((wgrp * 4 + nt) * 4 + kk) << 5) + lane];
#pragma unroll
            for (int mt = 0; mt < 4; mt++)
#pragma unroll
                for (int nt = 0; nt < 4; nt++)
                    mma_tf32(acc[mt][nt],
                             (const uint32_t*)&afr[mt],
                             (const uint32_t*)&bfr[nt]);
        }
        cstage = (cstage == GM_STAGES - 1) ? 0 : cstage + 1;
        lstage = (lstage == GM_STAGES - 1) ? 0 : lstage + 1;
    }

#pragma unroll
    for (int mt = 0; mt < 4; mt++) {
        const int row = m0 + wm2 * 64 + mt * 16 + gid;
#pragma unroll
        for (int nt = 0; nt < 4; nt++) {
            const int col = n0 + wgrp * 32 + nt * 8 + tig * 2;
            float2 bv = *(const float2*)(bias + col);
            float2 o0, o1;
            o0.x = acc[mt][nt][0] + bv.x;
            o0.y = acc[mt][nt][1] + bv.y;
            o1.x = acc[mt][nt][2] + bv.x;
            o1.y = acc[mt][nt][3] + bv.y;
            if (cvt_out) {
                o0.x = __uint_as_float(f2tf32(o0.x));
                o0.y = __uint_as_float(f2tf32(o0.y));
                o1.x = __uint_as_float(f2tf32(o1.x));
                o1.y = __uint_as_float(f2tf32(o1.y));
            }
            *(float2*)(C + (size_t)row * N + col) = o0;
            *(float2*)(C + (size_t)(row + 8) * N + col) = o1;
        }
    }
}

// ---------------------------------------------------------------------------
// Flash attention v3: 4 warps x 32 q-rows (2 m16-tiles per warp).
// K/V fragment loads amortized over 2x the MMAs -> crossbar traffic halved.
// 64-key smem tiles (double-buffered), processed as 2x32-key subtiles with
// online softmax per subtile (keeps live registers bounded).
// ---------------------------------------------------------------------------
#define ATP_ST_FL 8192
#define ATT_SMEM_BYTES (2 * ATP_ST_FL * 4)   // 65536

__global__ __launch_bounds__(128, 2) void attn_mma_kernel(
    const float* __restrict__ qkv, const float* __restrict__ kvp,
    float* __restrict__ vals)
{
    extern __shared__ float fsm[];
    const uint32_t sb = smem_u32(fsm);

    const int tid  = threadIdx.x;
    const int wid  = tid >> 5;       // 0..3
    const int lane = tid & 31;
    const int gid  = lane >> 2;
    const int tig  = lane & 3;
    const int b  = blockIdx.z;
    const int h  = blockIdx.y;
    const int q0 = blockIdx.x * 128;

    const float qscale = 0.125f * 1.4426950408889634f;

    // Q fragments for 32 rows: m-tile m covers rows q0+wid*32+m*16+{gid,gid+8}
    uint32_t qf[2][8][4];
#pragma unroll
    for (int m = 0; m < 2; m++) {
        const float* qlo = qkv + (size_t)(b * SS + q0 + wid * 32 + m * 16 + gid) * QKV_N + h * 192;
        const float* qhi = qlo + 8 * QKV_N;
#pragma unroll
        for (int kk = 0; kk < 8; kk++) {
            const int c = kk * 8 + tig;
            qf[m][kk][0] = f2tf32(qlo[c] * qscale);
            qf[m][kk][1] = f2tf32(qhi[c] * qscale);
            qf[m][kk][2] = f2tf32(qlo[c + 4] * qscale);
            qf[m][kk][3] = f2tf32(qhi[c + 4] * qscale);
        }
    }

    const float* kvbase = kvp + (size_t)(b * HH + h) * 32 * ATP_ST_FL;
    auto load_tile = [&](int kt) {
        const int stage = kt & 1;
        const float* src = kvbase + (size_t)kt * ATP_ST_FL;
        const uint32_t dst = sb + stage * (ATP_ST_FL * 4);
#pragma unroll
        for (int it = 0; it < 16; it++) {
            int idx = it * 128 + tid;
            asm volatile("cp.async.cg.shared.global [%0], [%1], 16;"
                         :: "r"(dst + idx * 16), "l"(src + idx * 4));
        }
    };

    float mx[2][2], lx[2][2];
#pragma unroll
    for (int m = 0; m < 2; m++) {
        mx[m][0] = mx[m][1] = -1e30f;
        lx[m][0] = lx[m][1] = 0.f;
    }
    float oacc[2][8][4];
#pragma unroll
    for (int m = 0; m < 2; m++)
#pragma unroll
        for (int nt = 0; nt < 8; nt++)
#pragma unroll
            for (int r = 0; r < 4; r++) oacc[m][nt][r] = 0.f;

    load_tile(0);
    asm volatile("cp.async.commit_group;" ::: "memory");

    const int NT = SS / 64;
    for (int kt = 0; kt < NT; kt++) {
        asm volatile("cp.async.wait_group 0;" ::: "memory");
        __syncthreads();
        if (kt + 1 < NT) {
            load_tile(kt + 1);
            asm volatile("cp.async.commit_group;" ::: "memory");
        }

        const int stage = kt & 1;
        const float2* kp2 = (const float2*)(fsm + stage * ATP_ST_FL);
        const float2* vp2 = kp2 + 2048;

#pragma unroll
        for (int st = 0; st < 2; st++) {   // 32-key subtiles
            // ---- S = Q @ K^T (32 rows x 32 keys) ----
            float sacc[2][4][4];
#pragma unroll
            for (int m = 0; m < 2; m++)
#pragma unroll
                for (int j = 0; j < 4; j++)
#pragma unroll
                    for (int r = 0; r < 4; r++) sacc[m][j][r] = 0.f;

#pragma unroll
            for (int kk = 0; kk < 8; kk++) {
                float2 kfr[4];
#pragma unroll
                for (int j = 0; j < 4; j++)
                    kfr[j] = kp2[((kk * 8 + st * 4 + j) << 5) + lane];
#pragma unroll
                for (int m = 0; m < 2; m++)
#pragma unroll
                    for (int j = 0; j < 4; j++)
                        mma_tf32(sacc[m][j], qf[m][kk], (const uint32_t*)&kfr[j]);
            }

            // ---- online softmax per m-tile ----
            uint32_t pf[2][4][4];
#pragma unroll
            for (int m = 0; m < 2; m++) {
                float tmax0 = -1e30f, tmax1 = -1e30f;
#pragma unroll
                for (int j = 0; j < 4; j++) {
                    tmax0 = fmaxf(tmax0, fmaxf(sacc[m][j][0], sacc[m][j][1]));
                    tmax1 = fmaxf(tmax1, fmaxf(sacc[m][j][2], sacc[m][j][3]));
                }
                tmax0 = fmaxf(tmax0, __shfl_xor_sync(0xffffffffu, tmax0, 1));
                tmax0 = fmaxf(tmax0, __shfl_xor_sync(0xffffffffu, tmax0, 2));
                tmax1 = fmaxf(tmax1, __shfl_xor_sync(0xffffffffu, tmax1, 1));
                tmax1 = fmaxf(tmax1, __shfl_xor_sync(0xffffffffu, tmax1, 2));

                const float mn0 = fmaxf(mx[m][0], tmax0);
                const float mn1 = fmaxf(mx[m][1], tmax1);
                const float corr0 = ex2(mx[m][0] - mn0);
                const float corr1 = ex2(mx[m][1] - mn1);
                mx[m][0] = mn0;
                mx[m][1] = mn1;

                float sum0 = 0.f, sum1 = 0.f;
#pragma unroll
                for (int j = 0; j < 4; j++) {
                    float p0 = ex2(sacc[m][j][0] - mn0);
                    float p1 = ex2(sacc[m][j][1] - mn0);
                    float p2 = ex2(sacc[m][j][2] - mn1);
                    float p3 = ex2(sacc[m][j][3] - mn1);
                    sum0 += p0 + p1;
                    sum1 += p2 + p3;
                    pf[m][j][0] = f2tf32(p0);
                    pf[m][j][1] = f2tf32(p2);
                    pf[m][j][2] = f2tf32(p1);
                    pf[m][j][3] = f2tf32(p3);
                }
#pragma unroll
                for (int nt = 0; nt < 8; nt++) {
                    oacc[m][nt][0] *= corr0;
                    oacc[m][nt][1] *= corr0;
                    oacc[m][nt][2] *= corr1;
                    oacc[m][nt][3] *= corr1;
                }
                sum0 += __shfl_xor_sync(0xffffffffu, sum0, 1);
                sum0 += __shfl_xor_sync(0xffffffffu, sum0, 2);
                sum1 += __shfl_xor_sync(0xffffffffu, sum1, 1);
                sum1 += __shfl_xor_sync(0xffffffffu, sum1, 2);
                lx[m][0] = lx[m][0] * corr0 + sum0;
                lx[m][1] = lx[m][1] * corr1 + sum1;
            }

            // ---- O += P @ V (32 keys) ----
#pragma unroll
            for (int j2 = 0; j2 < 4; j2++) {
                float2 vfr[8];
#pragma unroll
                for (int nt = 0; nt < 8; nt++)
                    vfr[nt] = vp2[(((st * 4 + j2) * 8 + nt) << 5) + lane];
#pragma unroll
                for (int m = 0; m < 2; m++)
#pragma unroll
                    for (int nt = 0; nt < 8; nt++)
                        mma_tf32(oacc[m][nt], pf[m][j2], (const uint32_t*)&vfr[nt]);
            }
        }
    }

    // ---- normalize + write out ----
#pragma unroll
    for (int m = 0; m < 2; m++) {
        const float inv0 = 1.f / lx[m][0];
        const float inv1 = 1.f / lx[m][1];
        float* olo = vals + (size_t)(b * SS + q0 + wid * 32 + m * 16 + gid) * DD + h * HDIM;
        float* ohi = olo + 8 * DD;
#pragma unroll
        for (int nt = 0; nt < 8; nt++) {
            const int c = nt * 8 + 2 * tig;
            float2 r0, r1;
            r0.x = oacc[m][nt][0] * inv0;
            r0.y = oacc[m][nt][1] * inv0;
            r1.x = oacc[m][nt][2] * inv1;
            r1.y = oacc[m][nt][3] * inv1;
            *(float2*)(olo + c) = r0;
            *(float2*)(ohi + c) = r1;
        }
    }
}

// ---------------------------------------------------------------------------
// Launch
// ---------------------------------------------------------------------------
extern "C" void kernel_launch(void* const* d_in, const int* in_sizes, int n_in,
                              void* d_out, int out_size)
{
    const float* x      = (const float*)d_in[0];
    const float* w_qkv  = (const float*)d_in[1];
    const float* b_qkv  = (const float*)d_in[2];
    const float* w_o    = (const float*)d_in[3];
    const float* b_o    = (const float*)d_in[4];
    float* out = (float*)d_out;

    float *qkv_buf, *vals_buf, *xc, *valsp, *wqc, *woc, *kvp;
    cudaGetSymbolAddress((void**)&qkv_buf, g_qkv);
    cudaGetSymbolAddress((void**)&vals_buf, g_vals);
    cudaGetSymbolAddress((void**)&xc,    g_xc);
    cudaGetSymbolAddress((void**)&valsp, g_valsp);
    cudaGetSymbolAddress((void**)&wqc,   g_wqc);
    cudaGetSymbolAddress((void**)&woc,   g_woc);
    cudaGetSymbolAddress((void**)&kvp,   g_kvp);

    cudaFuncSetAttribute(gemm_mma_kernel,
                         cudaFuncAttributeMaxDynamicSharedMemorySize,
                         GEMM_SMEM_BYTES);
    cudaFuncSetAttribute(attn_mma_kernel,
                         cudaFuncAttributeMaxDynamicSharedMemorySize,
                         ATT_SMEM_BYTES);

    // 0) fragment-pack GEMM inputs (with tf32 rounding)
    pack_a_kernel<<<(M_ROWS / 128) * (DIN / 32), 256>>>(x, xc, DIN);
    pack_b_kernel<<<(QKV_N / 128) * (DIN / 32), 256>>>(w_qkv, wqc, DIN);
    pack_b_kernel<<<(DD / 128) * (DIN / 32), 256>>>(w_o, woc, DIN);

    // 1) QKV projection -> g_qkv (row-major, tf32-rounded)
    {
        dim3 grid(QKV_N / 128, M_ROWS / 128);
        gemm_mma_kernel<<<grid, 256, GEMM_SMEM_BYTES>>>(
            xc, wqc, b_qkv, qkv_buf, M_ROWS, QKV_N, DIN, 1);
    }

    // 1b) fragment-pack K/V tiles
    {
        dim3 grid(SS / 64, HH, BB);
        pack_kv_kernel<<<grid, 256>>>(qkv_buf, kvp);
    }

    // 2) Attention -> g_vals (row-major)
    {
        dim3 grid(SS / 128, HH, BB);
        attn_mma_kernel<<<grid, 128, ATT_SMEM_BYTES>>>(qkv_buf, kvp, vals_buf);
    }

    // 3) pack attention output, then O-projection -> out
    pack_a_kernel<<<(M_ROWS / 128) * (DD / 32), 256>>>(vals_buf, valsp, DD);
    {
        dim3 grid(DD / 128, M_ROWS / 128);
        gemm_mma_kernel<<<grid, 256, GEMM_SMEM_BYTES>>>(
            valsp, woc, b_o, out, M_ROWS, DD, DIN, 0);
    }
}

// round 10
// speedup vs baseline: 9.0036x; 1.6675x over previous
#include <cuda_runtime.h>
#include <cuda_fp16.h>
#include <cstdint>
#include <math.h>

// Problem constants
#define BB   2
#define SS   2048
#define DIN  1024
#define DD   1024
#define HH   16
#define HDIM 64
#define M_ROWS (BB * SS)      // 4096
#define QKV_N  (3 * DD)       // 3072

// Scratch
__device__ float  g_qkv  [M_ROWS * QKV_N];      // qkv row-major fp32
__device__ float  g_vals [M_ROWS * DD];         // attention out fp32
__device__ __half g_xc   [M_ROWS * DIN];        // x, fp16 fragment-packed
__device__ __half g_valsp[M_ROWS * DD];         // vals, fp16 fragment-packed
__device__ __half g_wqc  [QKV_N * DIN];         // w_qkv, fp16 fragment-packed
__device__ __half g_woc  [DD * DD];             // w_o, fp16 fragment-packed
__device__ __half g_kvp  [BB * HH * 32 * 8192]; // K/V fp16 fragment-packed

// ---------------------------------------------------------------------------
// Helpers
// ---------------------------------------------------------------------------
__device__ __forceinline__ uint32_t smem_u32(const void* p) {
    uint32_t a;
    asm("{ .reg .u64 t; cvta.to.shared.u64 t, %1; cvt.u32.u64 %0, t; }"
        : "=r"(a) : "l"(p));
    return a;
}

__device__ __forceinline__ uint32_t f2h2(float a, float b) {
    __half2 h = __floats2half2_rn(a, b);
    return *(uint32_t*)&h;
}

__device__ __forceinline__ float ex2(float x) {
    float r;
    asm("ex2.approx.f32 %0, %1;" : "=f"(r) : "f"(x));
    return r;
}

// m16n8k16 fp16 MMA, fp32 accumulate.
__device__ __forceinline__ void mma_f16(float* d, const uint32_t* a, const uint32_t* b) {
    asm("mma.sync.aligned.m16n8k16.row.col.f32.f16.f16.f32 "
        "{%0,%1,%2,%3}, {%4,%5,%6,%7}, {%8,%9}, {%0,%1,%2,%3};"
        : "+f"(d[0]), "+f"(d[1]), "+f"(d[2]), "+f"(d[3])
        : "r"(a[0]), "r"(a[1]), "r"(a[2]), "r"(a[3]),
          "r"(b[0]), "r"(b[1]));
}

// ---------------------------------------------------------------------------
// Pack kernels: fp32 row-major -> fp16 fragment-order chunks.
// Tile = 128 rows x 64 k. A-chunk (uint4, per lane): m16n8k16 A fragment
//   {A[r0][kb],A[r0][kb+1] | A[r0+8][kb],+1 | A[r0][kb+8],+9 | A[r0+8][kb+8],+9}
//   r0 = grp*16+gid, kb = ks*16+2*tig; chunk idx = (grp*4+ks)*32+lane.
// B-chunk (uint2): {B[n][kb],+1 | B[n][kb+8],+9}, n = ngrp*8+gid;
//   chunk idx = (ngrp*4+ks)*32+lane.
// ---------------------------------------------------------------------------
#define PSTR 68

__global__ __launch_bounds__(256) void pack_a_h(
    const float* __restrict__ src, __half* __restrict__ dst, int K)
{
    __shared__ float sm[128 * PSTR];
    const int tid = threadIdx.x;
    const int KT = K / 64;
    const int kt = blockIdx.x % KT;
    const int mt = blockIdx.x / KT;
    const float* g = src + (size_t)(mt * 128) * K + kt * 64;
#pragma unroll
    for (int it = 0; it < 8; it++) {
        int idx = it * 256 + tid;
        int r = idx >> 4;
        int c4 = (idx & 15) * 4;
        *(float4*)&sm[r * PSTR + c4] = *(const float4*)(g + (size_t)r * K + c4);
    }
    __syncthreads();
    uint4* o = (uint4*)(dst + (size_t)blockIdx.x * 8192);
#pragma unroll
    for (int it = 0; it < 4; it++) {
        int q = it * 256 + tid;          // 0..1023
        int grp = q >> 7;
        int ks = (q >> 5) & 3;
        int lane = q & 31;
        int gid = lane >> 2, tig = lane & 3;
        int r0 = grp * 16 + gid;
        int kb = ks * 16 + 2 * tig;
        uint4 w;
        w.x = f2h2(sm[r0 * PSTR + kb],           sm[r0 * PSTR + kb + 1]);
        w.y = f2h2(sm[(r0 + 8) * PSTR + kb],     sm[(r0 + 8) * PSTR + kb + 1]);
        w.z = f2h2(sm[r0 * PSTR + kb + 8],       sm[r0 * PSTR + kb + 9]);
        w.w = f2h2(sm[(r0 + 8) * PSTR + kb + 8], sm[(r0 + 8) * PSTR + kb + 9]);
        o[q] = w;
    }
}

__global__ __launch_bounds__(256) void pack_b_h(
    const float* __restrict__ src, __half* __restrict__ dst, int K)
{
    __shared__ float sm[128 * PSTR];
    const int tid = threadIdx.x;
    const int KT = K / 64;
    const int kt = blockIdx.x % KT;
    const int nt = blockIdx.x / KT;
    const float* g = src + (size_t)(nt * 128) * K + kt * 64;
#pragma unroll
    for (int it = 0; it < 8; it++) {
        int idx = it * 256 + tid;
        int r = idx >> 4;
        int c4 = (idx & 15) * 4;
        *(float4*)&sm[r * PSTR + c4] = *(const float4*)(g + (size_t)r * K + c4);
    }
    __syncthreads();
    uint2* o = (uint2*)(dst + (size_t)blockIdx.x * 8192);
#pragma unroll
    for (int it = 0; it < 8; it++) {
        int q = it * 256 + tid;          // 0..2047
        int ngrp = q >> 7;               // 0..15
        int ks = (q >> 5) & 3;
        int lane = q & 31;
        int gid = lane >> 2, tig = lane & 3;
        int n = ngrp * 8 + gid;
        int kb = ks * 16 + 2 * tig;
        uint2 w;
        w.x = f2h2(sm[n * PSTR + kb],     sm[n * PSTR + kb + 1]);
        w.y = f2h2(sm[n * PSTR + kb + 8], sm[n * PSTR + kb + 9]);
        o[q] = w;
    }
}

// K/V pack: one block per (b, h, 64-key tile). Out tile 8192 half:
//  K chunks (1024 uint2): idx (nt*4+ks)*32+lane:
//    {K[key][kb],+1 | K[key][kb+8],+9}, key = nt*8+gid, kb = ks*16+2tig
//  V chunks (1024 uint2): idx (j*8+nt)*32+lane:
//    {V[16j+2tig][d], V[16j+2tig+1][d] | V[16j+2tig+8][d], V[16j+2tig+9][d]},
//    d = nt*8+gid
__global__ __launch_bounds__(256) void pack_kv_h(
    const float* __restrict__ qkv, __half* __restrict__ kvp)
{
    __shared__ float ksm[64 * PSTR];
    __shared__ float vsm[64 * PSTR];
    const int tid = threadIdx.x;
    const int kt = blockIdx.x;
    const int h  = blockIdx.y;
    const int b  = blockIdx.z;

    const float* src = qkv + (size_t)(b * SS + kt * 64) * QKV_N + h * 192 + 64;
#pragma unroll
    for (int it = 0; it < 4; it++) {
        int idx = it * 256 + tid;
        int row = idx >> 4;
        int c4  = (idx & 15) * 4;
        const float* g = src + (size_t)row * QKV_N + c4;
        *(float4*)&ksm[row * PSTR + c4] = *(const float4*)g;
        *(float4*)&vsm[row * PSTR + c4] = *(const float4*)(g + 64);
    }
    __syncthreads();

    uint2* ko = (uint2*)(kvp + (size_t)((b * HH + h) * 32 + kt) * 8192);
    uint2* vo = ko + 1024;
#pragma unroll
    for (int it = 0; it < 4; it++) {
        int q = it * 256 + tid;          // 0..1023
        int lane = q & 31;
        int gid = lane >> 2, tig = lane & 3;
        // K chunk
        int nt = q >> 7;
        int ks = (q >> 5) & 3;
        int key = nt * 8 + gid;
        int kb = ks * 16 + 2 * tig;
        uint2 kw;
        kw.x = f2h2(ksm[key * PSTR + kb],     ksm[key * PSTR + kb + 1]);
        kw.y = f2h2(ksm[key * PSTR + kb + 8], ksm[key * PSTR + kb + 9]);
        ko[q] = kw;
        // V chunk
        int j = q >> 8;                  // 0..3
        int nt2 = (q >> 5) & 7;          // 0..7
        int d = nt2 * 8 + gid;
        int kr = j * 16 + 2 * tig;
        uint2 vw;
        vw.x = f2h2(vsm[kr * PSTR + d],       vsm[(kr + 1) * PSTR + d]);
        vw.y = f2h2(vsm[(kr + 8) * PSTR + d], vsm[(kr + 9) * PSTR + d]);
        vo[q] = vw;
    }
}

// ---------------------------------------------------------------------------
// fp16 mma.sync GEMM on fragment-packed operands: C = A @ Bw^T + bias.
// 128x128 CTA, BK=64, 256 thr (8 warps 2x4), warp tile 64x32, 3-stage pipe.
// Tile = 16KB (A: 1024 uint4, B: 2048 uint2).
// ---------------------------------------------------------------------------
#define GM_STAGES 3
#define GEMM_SMEM_BYTES (2 * GM_STAGES * 16384)   // 98304

__global__ __launch_bounds__(256, 2) void gemm_h(
    const __half* __restrict__ A, const __half* __restrict__ Bw,
    const float* __restrict__ bias, float* __restrict__ C,
    int M, int N, int K)
{
    extern __shared__ char smc[];
    const uint32_t sb = smem_u32(smc);
    const int tid  = threadIdx.x;
    const int wid  = tid >> 5;
    const int lane = tid & 31;
    const int gid  = lane >> 2;
    const int tig  = lane & 3;
    const int wm2  = wid >> 2;
    const int wgrp = wid & 3;
    const int m0 = blockIdx.y * 128;
    const int n0 = blockIdx.x * 128;
    const int KT = K / 64;

    float acc[4][4][4];
#pragma unroll
    for (int i = 0; i < 4; i++)
#pragma unroll
        for (int j = 0; j < 4; j++)
#pragma unroll
            for (int r = 0; r < 4; r++) acc[i][j][r] = 0.f;

    auto load_stage = [&](int chunk, int stage) {
        const uint4* ag = (const uint4*)A + ((size_t)blockIdx.y * KT + chunk) * 1024;
        const uint4* bg = (const uint4*)Bw + ((size_t)blockIdx.x * KT + chunk) * 1024;
        const uint32_t a_s = sb + stage * 16384;
        const uint32_t b_s = sb + GM_STAGES * 16384 + stage * 16384;
#pragma unroll
        for (int it = 0; it < 4; it++) {
            int idx = it * 256 + tid;
            asm volatile("cp.async.cg.shared.global [%0], [%1], 16;"
                         :: "r"(a_s + idx * 16), "l"(ag + idx));
            asm volatile("cp.async.cg.shared.global [%0], [%1], 16;"
                         :: "r"(b_s + idx * 16), "l"(bg + idx));
        }
    };

    load_stage(0, 0);
    asm volatile("cp.async.commit_group;" ::: "memory");
    load_stage(1, 1);
    asm volatile("cp.async.commit_group;" ::: "memory");

    int cstage = 0;
    int lstage = 2;
    for (int j = 0; j < KT; j++) {
        if (j + 1 < KT) {
            asm volatile("cp.async.wait_group 1;" ::: "memory");
        } else {
            asm volatile("cp.async.wait_group 0;" ::: "memory");
        }
        __syncthreads();
        if (j + 2 < KT) {
            load_stage(j + 2, lstage);
            asm volatile("cp.async.commit_group;" ::: "memory");
        }

        const uint4* at4 = (const uint4*)(smc + cstage * 16384);
        const uint2* bt2 = (const uint2*)(smc + GM_STAGES * 16384 + cstage * 16384);

#pragma unroll
        for (int ks = 0; ks < 4; ks++) {
            uint4 afr[4];
#pragma unroll
            for (int mt = 0; mt < 4; mt++)
                afr[mt] = at4[(((wm2 * 4 + mt) * 4 + ks) << 5) + lane];
            uint2 bfr[4];
#pragma unroll
            for (int nt = 0; nt < 4; nt++)
                bfr[nt] = bt2[(((wgrp * 4 + nt) * 4 + ks) << 5) + lane];
#pragma unroll
            for (int mt = 0; mt < 4; mt++)
#pragma unroll
                for (int nt = 0; nt < 4; nt++)
                    mma_f16(acc[mt][nt],
                            (const uint32_t*)&afr[mt],
                            (const uint32_t*)&bfr[nt]);
        }
        cstage = (cstage == GM_STAGES - 1) ? 0 : cstage + 1;
        lstage = (lstage == GM_STAGES - 1) ? 0 : lstage + 1;
    }

#pragma unroll
    for (int mt = 0; mt < 4; mt++) {
        const int row = m0 + wm2 * 64 + mt * 16 + gid;
#pragma unroll
        for (int nt = 0; nt < 4; nt++) {
            const int col = n0 + wgrp * 32 + nt * 8 + tig * 2;
            float2 bv = *(const float2*)(bias + col);
            float2 o0, o1;
            o0.x = acc[mt][nt][0] + bv.x;
            o0.y = acc[mt][nt][1] + bv.y;
            o1.x = acc[mt][nt][2] + bv.x;
            o1.y = acc[mt][nt][3] + bv.y;
            *(float2*)(C + (size_t)row * N + col) = o0;
            *(float2*)(C + (size_t)(row + 8) * N + col) = o1;
        }
    }
}

// ---------------------------------------------------------------------------
// fp16 flash attention: 4 warps x 32 q-rows, 64-key tiles double-buffered.
// m16n8k16: HD=64 -> 4 k-steps for QK; 64 keys -> 4 k-steps for PV.
// P A-fragments come straight from S accumulators: k-halves {0-7|8-15} map
// onto sacc n8-group pairs (2j, 2j+1); V packed in natural key order.
// ---------------------------------------------------------------------------
#define ATT_SMEM_BYTES (2 * 16384)   // 32768

__global__ __launch_bounds__(128, 2) void attn_h(
    const float* __restrict__ qkv, const __half* __restrict__ kvp,
    float* __restrict__ vals)
{
    extern __shared__ char smc[];
    const uint32_t sb = smem_u32(smc);

    const int tid  = threadIdx.x;
    const int wid  = tid >> 5;       // 0..3
    const int lane = tid & 31;
    const int gid  = lane >> 2;
    const int tig  = lane & 3;
    const int b  = blockIdx.z;
    const int h  = blockIdx.y;
    const int q0 = blockIdx.x * 128;

    const float qs = 0.125f * 1.4426950408889634f;

    // Q fragments (fp16), 2 m16-tiles per warp, 4 k16-steps.
    uint32_t qf[2][4][4];
#pragma unroll
    for (int m = 0; m < 2; m++) {
        const float* qlo = qkv + (size_t)(b * SS + q0 + wid * 32 + m * 16 + gid) * QKV_N + h * 192;
        const float* qhi = qlo + 8 * QKV_N;
#pragma unroll
        for (int ks = 0; ks < 4; ks++) {
            const int kb = ks * 16 + 2 * tig;
            qf[m][ks][0] = f2h2(qlo[kb] * qs,     qlo[kb + 1] * qs);
            qf[m][ks][1] = f2h2(qhi[kb] * qs,     qhi[kb + 1] * qs);
            qf[m][ks][2] = f2h2(qlo[kb + 8] * qs, qlo[kb + 9] * qs);
            qf[m][ks][3] = f2h2(qhi[kb + 8] * qs, qhi[kb + 9] * qs);
        }
    }

    const __half* kvbase = kvp + (size_t)(b * HH + h) * 32 * 8192;
    auto load_tile = [&](int kt) {
        const uint4* src = (const uint4*)(kvbase + (size_t)kt * 8192);
        const uint32_t dst = sb + (kt & 1) * 16384;
#pragma unroll
        for (int it = 0; it < 8; it++) {
            int idx = it * 128 + tid;
            asm volatile("cp.async.cg.shared.global [%0], [%1], 16;"
                         :: "r"(dst + idx * 16), "l"(src + idx));
        }
    };

    float mx[2][2], lx[2][2];
#pragma unroll
    for (int m = 0; m < 2; m++) {
        mx[m][0] = mx[m][1] = -1e30f;
        lx[m][0] = lx[m][1] = 0.f;
    }
    float oacc[2][8][4];
#pragma unroll
    for (int m = 0; m < 2; m++)
#pragma unroll
        for (int nt = 0; nt < 8; nt++)
#pragma unroll
            for (int r = 0; r < 4; r++) oacc[m][nt][r] = 0.f;

    load_tile(0);
    asm volatile("cp.async.commit_group;" ::: "memory");

    const int NT = SS / 64;
    for (int kt = 0; kt < NT; kt++) {
        asm volatile("cp.async.wait_group 0;" ::: "memory");
        __syncthreads();
        if (kt + 1 < NT) {
            load_tile(kt + 1);
            asm volatile("cp.async.commit_group;" ::: "memory");
        }

        const uint2* kp2 = (const uint2*)(smc + (kt & 1) * 16384);
        const uint2* vp2 = kp2 + 1024;

        // ---- S = Q @ K^T (32 rows x 64 keys per warp) ----
        float sacc[2][8][4];
#pragma unroll
        for (int m = 0; m < 2; m++)
#pragma unroll
            for (int nt = 0; nt < 8; nt++)
#pragma unroll
                for (int r = 0; r < 4; r++) sacc[m][nt][r] = 0.f;

#pragma unroll
        for (int ks = 0; ks < 4; ks++) {
            uint2 kfr[8];
#pragma unroll
            for (int nt = 0; nt < 8; nt++)
                kfr[nt] = kp2[((nt * 4 + ks) << 5) + lane];
#pragma unroll
            for (int m = 0; m < 2; m++)
#pragma unroll
                for (int nt = 0; nt < 8; nt++)
                    mma_f16(sacc[m][nt], qf[m][ks], (const uint32_t*)&kfr[nt]);
        }

        // ---- online softmax + build fp16 P fragments ----
        uint32_t pf[2][4][4];
#pragma unroll
        for (int m = 0; m < 2; m++) {
            float tmax0 = -1e30f, tmax1 = -1e30f;
#pragma unroll
            for (int nt = 0; nt < 8; nt++) {
                tmax0 = fmaxf(tmax0, fmaxf(sacc[m][nt][0], sacc[m][nt][1]));
                tmax1 = fmaxf(tmax1, fmaxf(sacc[m][nt][2], sacc[m][nt][3]));
            }
            tmax0 = fmaxf(tmax0, __shfl_xor_sync(0xffffffffu, tmax0, 1));
            tmax0 = fmaxf(tmax0, __shfl_xor_sync(0xffffffffu, tmax0, 2));
            tmax1 = fmaxf(tmax1, __shfl_xor_sync(0xffffffffu, tmax1, 1));
            tmax1 = fmaxf(tmax1, __shfl_xor_sync(0xffffffffu, tmax1, 2));

            const float mn0 = fmaxf(mx[m][0], tmax0);
            const float mn1 = fmaxf(mx[m][1], tmax1);
            const float corr0 = ex2(mx[m][0] - mn0);
            const float corr1 = ex2(mx[m][1] - mn1);
            mx[m][0] = mn0;
            mx[m][1] = mn1;

            float sum0 = 0.f, sum1 = 0.f;
#pragma unroll
            for (int nt = 0; nt < 8; nt++) {
                float p0 = ex2(sacc[m][nt][0] - mn0);
                float p1 = ex2(sacc[m][nt][1] - mn0);
                float p2 = ex2(sacc[m][nt][2] - mn1);
                float p3 = ex2(sacc[m][nt][3] - mn1);
                sum0 += p0 + p1;
                sum1 += p2 + p3;
                const int j = nt >> 1;
                if ((nt & 1) == 0) {
                    pf[m][j][0] = f2h2(p0, p1);
                    pf[m][j][1] = f2h2(p2, p3);
                } else {
                    pf[m][j][2] = f2h2(p0, p1);
                    pf[m][j][3] = f2h2(p2, p3);
                }
            }
#pragma unroll
            for (int nt = 0; nt < 8; nt++) {
                oacc[m][nt][0] *= corr0;
                oacc[m][nt][1] *= corr0;
                oacc[m][nt][2] *= corr1;
                oacc[m][nt][3] *= corr1;
            }
            sum0 += __shfl_xor_sync(0xffffffffu, sum0, 1);
            sum0 += __shfl_xor_sync(0xffffffffu, sum0, 2);
            sum1 += __shfl_xor_sync(0xffffffffu, sum1, 1);
            sum1 += __shfl_xor_sync(0xffffffffu, sum1, 2);
            lx[m][0] = lx[m][0] * corr0 + sum0;
            lx[m][1] = lx[m][1] * corr1 + sum1;
        }

        // ---- O += P @ V (4 k16-steps over 64 keys) ----
#pragma unroll
        for (int j = 0; j < 4; j++) {
            uint2 vfr[8];
#pragma unroll
            for (int nt = 0; nt < 8; nt++)
                vfr[nt] = vp2[((j * 8 + nt) << 5) + lane];
#pragma unroll
            for (int m = 0; m < 2; m++)
#pragma unroll
                for (int nt = 0; nt < 8; nt++)
                    mma_f16(oacc[m][nt], pf[m][j], (const uint32_t*)&vfr[nt]);
        }
    }

    // ---- normalize + write out ----
#pragma unroll
    for (int m = 0; m < 2; m++) {
        const float inv0 = 1.f / lx[m][0];
        const float inv1 = 1.f / lx[m][1];
        float* olo = vals + (size_t)(b * SS + q0 + wid * 32 + m * 16 + gid) * DD + h * HDIM;
        float* ohi = olo + 8 * DD;
#pragma unroll
        for (int nt = 0; nt < 8; nt++) {
            const int c = nt * 8 + 2 * tig;
            float2 r0, r1;
            r0.x = oacc[m][nt][0] * inv0;
            r0.y = oacc[m][nt][1] * inv0;
            r1.x = oacc[m][nt][2] * inv1;
            r1.y = oacc[m][nt][3] * inv1;
            *(float2*)(olo + c) = r0;
            *(float2*)(ohi + c) = r1;
        }
    }
}

// ---------------------------------------------------------------------------
// Launch
// ---------------------------------------------------------------------------
extern "C" void kernel_launch(void* const* d_in, const int* in_sizes, int n_in,
                              void* d_out, int out_size)
{
    const float* x      = (const float*)d_in[0];
    const float* w_qkv  = (const float*)d_in[1];
    const float* b_qkv  = (const float*)d_in[2];
    const float* w_o    = (const float*)d_in[3];
    const float* b_o    = (const float*)d_in[4];
    float* out = (float*)d_out;

    float *qkv_buf, *vals_buf;
    __half *xc, *valsp, *wqc, *woc, *kvp;
    cudaGetSymbolAddress((void**)&qkv_buf, g_qkv);
    cudaGetSymbolAddress((void**)&vals_buf, g_vals);
    cudaGetSymbolAddress((void**)&xc,    g_xc);
    cudaGetSymbolAddress((void**)&valsp, g_valsp);
    cudaGetSymbolAddress((void**)&wqc,   g_wqc);
    cudaGetSymbolAddress((void**)&woc,   g_woc);
    cudaGetSymbolAddress((void**)&kvp,   g_kvp);

    cudaFuncSetAttribute(gemm_h,
                         cudaFuncAttributeMaxDynamicSharedMemorySize,
                         GEMM_SMEM_BYTES);
    cudaFuncSetAttribute(attn_h,
                         cudaFuncAttributeMaxDynamicSharedMemorySize,
                         ATT_SMEM_BYTES);

    // 0) fragment-pack GEMM inputs into fp16
    pack_a_h<<<(M_ROWS / 128) * (DIN / 64), 256>>>(x, xc, DIN);
    pack_b_h<<<(QKV_N / 128) * (DIN / 64), 256>>>(w_qkv, wqc, DIN);
    pack_b_h<<<(DD / 128) * (DIN / 64), 256>>>(w_o, woc, DIN);

    // 1) QKV projection -> g_qkv (fp32 row-major)
    {
        dim3 grid(QKV_N / 128, M_ROWS / 128);
        gemm_h<<<grid, 256, GEMM_SMEM_BYTES>>>(
            xc, wqc, b_qkv, qkv_buf, M_ROWS, QKV_N, DIN);
    }

    // 1b) fragment-pack K/V tiles into fp16
    {
        dim3 grid(SS / 64, HH, BB);
        pack_kv_h<<<grid, 256>>>(qkv_buf, kvp);
    }

    // 2) Attention -> g_vals (fp32 row-major)
    {
        dim3 grid(SS / 128, HH, BB);
        attn_h<<<grid, 128, ATT_SMEM_BYTES>>>(qkv_buf, kvp, vals_buf);
    }

    // 3) pack attention output, then O-projection -> out
    pack_a_h<<<(M_ROWS / 128) * (DD / 64), 256>>>(vals_buf, valsp, DD);
    {
        dim3 grid(DD / 128, M_ROWS / 128);
        gemm_h<<<grid, 256, GEMM_SMEM_BYTES>>>(
            valsp, woc, b_o, out, M_ROWS, DD, DIN);
    }
}

// round 12
// speedup vs baseline: 9.8144x; 1.0901x over previous
#include <cuda_runtime.h>
#include <cuda_fp16.h>
#include <cstdint>
#include <math.h>

// Problem constants
#define BB   2
#define SS   2048
#define DIN  1024
#define DD   1024
#define HH   16
#define HDIM 64
#define M_ROWS (BB * SS)      // 4096
#define QKV_N  (3 * DD)       // 3072

// Scratch
__device__ __half g_qkvh [M_ROWS * QKV_N];      // qkv row-major fp16
__device__ __half g_xc   [M_ROWS * DIN];        // x, fp16 fragment-packed
__device__ __half g_valsp[M_ROWS * DD];         // attn out, fp16 A-frag-packed
__device__ __half g_wqc  [QKV_N * DIN];         // w_qkv, fp16 fragment-packed
__device__ __half g_woc  [DD * DD];             // w_o, fp16 fragment-packed
__device__ __half g_kvp  [BB * HH * 32 * 8192]; // K/V fp16 fragment-packed

// ---------------------------------------------------------------------------
// Helpers
// ---------------------------------------------------------------------------
__device__ __forceinline__ uint32_t smem_u32(const void* p) {
    uint32_t a;
    asm("{ .reg .u64 t; cvta.to.shared.u64 t, %1; cvt.u32.u64 %0, t; }"
        : "=r"(a) : "l"(p));
    return a;
}

__device__ __forceinline__ uint32_t f2h2(float a, float b) {
    __half2 h = __floats2half2_rn(a, b);
    return *(uint32_t*)&h;
}

__device__ __forceinline__ float ex2(float x) {
    float r;
    asm("ex2.approx.f32 %0, %1;" : "=f"(r) : "f"(x));
    return r;
}

__device__ __forceinline__ void mma_f16(float* d, const uint32_t* a, const uint32_t* b) {
    asm("mma.sync.aligned.m16n8k16.row.col.f32.f16.f16.f32 "
        "{%0,%1,%2,%3}, {%4,%5,%6,%7}, {%8,%9}, {%0,%1,%2,%3};"
        : "+f"(d[0]), "+f"(d[1]), "+f"(d[2]), "+f"(d[3])
        : "r"(a[0]), "r"(a[1]), "r"(a[2]), "r"(a[3]),
          "r"(b[0]), "r"(b[1]));
}

// ---------------------------------------------------------------------------
// Pack kernels (fp32 sources: x, w_qkv, w_o).
// A chunk (uint4) idx (grp*4+ks)*32+lane, grp=row/16, r0=grp*16+gid, kb=16ks+2tig:
//   { [r0][kb],+1 | [r0+8][kb],+1 | [r0][kb+8],+9 | [r0+8][kb+8],+9 }
// B chunk (uint2) idx (ngrp*4+ks)*32+lane, n=ngrp*8+gid:
//   { [n][kb],+1 | [n][kb+8],+9 }
// ---------------------------------------------------------------------------
#define PSTR 68

__global__ __launch_bounds__(256) void pack_a_h(
    const float* __restrict__ src, __half* __restrict__ dst, int K)
{
    __shared__ float sm[128 * PSTR];
    const int tid = threadIdx.x;
    const int KT = K / 64;
    const int kt = blockIdx.x % KT;
    const int mt = blockIdx.x / KT;
    const float* g = src + (size_t)(mt * 128) * K + kt * 64;
#pragma unroll
    for (int it = 0; it < 8; it++) {
        int idx = it * 256 + tid;
        int r = idx >> 4;
        int c4 = (idx & 15) * 4;
        *(float4*)&sm[r * PSTR + c4] = *(const float4*)(g + (size_t)r * K + c4);
    }
    __syncthreads();
    uint4* o = (uint4*)(dst + (size_t)blockIdx.x * 8192);
#pragma unroll
    for (int it = 0; it < 4; it++) {
        int q = it * 256 + tid;
        int grp = q >> 7;
        int ks = (q >> 5) & 3;
        int lane = q & 31;
        int gid = lane >> 2, tig = lane & 3;
        int r0 = grp * 16 + gid;
        int kb = ks * 16 + 2 * tig;
        uint4 w;
        w.x = f2h2(sm[r0 * PSTR + kb],           sm[r0 * PSTR + kb + 1]);
        w.y = f2h2(sm[(r0 + 8) * PSTR + kb],     sm[(r0 + 8) * PSTR + kb + 1]);
        w.z = f2h2(sm[r0 * PSTR + kb + 8],       sm[r0 * PSTR + kb + 9]);
        w.w = f2h2(sm[(r0 + 8) * PSTR + kb + 8], sm[(r0 + 8) * PSTR + kb + 9]);
        o[q] = w;
    }
}

__global__ __launch_bounds__(256) void pack_b_h(
    const float* __restrict__ src, __half* __restrict__ dst, int K)
{
    __shared__ float sm[128 * PSTR];
    const int tid = threadIdx.x;
    const int KT = K / 64;
    const int kt = blockIdx.x % KT;
    const int nt = blockIdx.x / KT;
    const float* g = src + (size_t)(nt * 128) * K + kt * 64;
#pragma unroll
    for (int it = 0; it < 8; it++) {
        int idx = it * 256 + tid;
        int r = idx >> 4;
        int c4 = (idx & 15) * 4;
        *(float4*)&sm[r * PSTR + c4] = *(const float4*)(g + (size_t)r * K + c4);
    }
    __syncthreads();
    uint2* o = (uint2*)(dst + (size_t)blockIdx.x * 8192);
#pragma unroll
    for (int it = 0; it < 8; it++) {
        int q = it * 256 + tid;
        int ngrp = q >> 7;
        int ks = (q >> 5) & 3;
        int lane = q & 31;
        int gid = lane >> 2, tig = lane & 3;
        int n = ngrp * 8 + gid;
        int kb = ks * 16 + 2 * tig;
        uint2 w;
        w.x = f2h2(sm[n * PSTR + kb],     sm[n * PSTR + kb + 1]);
        w.y = f2h2(sm[n * PSTR + kb + 8], sm[n * PSTR + kb + 9]);
        o[q] = w;
    }
}

// ---------------------------------------------------------------------------
// K/V pack from fp16 qkv. One block per (b, h, 64-key tile).
// HSTR = 136 halves = 272 bytes (16B-aligned rows; fixes the r11 crash).
// ---------------------------------------------------------------------------
#define HSTR 136
__global__ __launch_bounds__(256) void pack_kv_h(
    const __half* __restrict__ qkvh, __half* __restrict__ kvp)
{
    __shared__ __half kv[64 * HSTR];   // per row: [K 64 halves | V 64 halves]
    const int tid = threadIdx.x;
    const int kt = blockIdx.x;
    const int h  = blockIdx.y;
    const int b  = blockIdx.z;

    const __half* src = qkvh + (size_t)(b * SS + kt * 64) * QKV_N + h * 192 + 64;
#pragma unroll
    for (int it = 0; it < 4; it++) {
        int idx = it * 256 + tid;          // 0..1023
        int row = idx >> 4;                // 0..63
        int c8  = (idx & 15) * 8;          // 0..120
        *(uint4*)&kv[row * HSTR + c8] = *(const uint4*)(src + (size_t)row * QKV_N + c8);
    }
    __syncthreads();

    uint2* ko = (uint2*)(kvp + (size_t)((b * HH + h) * 32 + kt) * 8192);
    uint2* vo = ko + 1024;
#pragma unroll
    for (int it = 0; it < 4; it++) {
        int q = it * 256 + tid;
        int lane = q & 31;
        int gid = lane >> 2, tig = lane & 3;
        // K chunk: idx (nt*4+ks)*32+lane
        {
            int nt = q >> 7;
            int ks = (q >> 5) & 3;
            int key = nt * 8 + gid;
            int kb = ks * 16 + 2 * tig;
            uint2 w;
            w.x = *(const uint32_t*)&kv[key * HSTR + kb];
            w.y = *(const uint32_t*)&kv[key * HSTR + kb + 8];
            ko[q] = w;
        }
        // V chunk: idx (j*8+nt)*32+lane
        {
            int j = q >> 8;
            int nt2 = (q >> 5) & 7;
            int d = 64 + nt2 * 8 + gid;    // V columns at +64
            int kr = j * 16 + 2 * tig;
            __half2 a = __halves2half2(kv[kr * HSTR + d],       kv[(kr + 1) * HSTR + d]);
            __half2 c = __halves2half2(kv[(kr + 8) * HSTR + d], kv[(kr + 9) * HSTR + d]);
            uint2 w;
            w.x = *(uint32_t*)&a;
            w.y = *(uint32_t*)&c;
            vo[q] = w;
        }
    }
}

// ---------------------------------------------------------------------------
// fp16 GEMM, warp tile 64x64: CTA 128x128, 4 warps (2x2), 2 CTA/SM.
// BK=64, 3-stage cp.async. Output fp32 (C) or fp16 row-major (Ch).
// ---------------------------------------------------------------------------
#define GM_STAGES 3
#define GEMM_SMEM_BYTES (2 * GM_STAGES * 16384)   // 98304

__global__ __launch_bounds__(128, 2) void gemm_h(
    const __half* __restrict__ A, const __half* __restrict__ Bw,
    const float* __restrict__ bias, float* __restrict__ C,
    __half* __restrict__ Ch,
    int M, int N, int K, int out_half)
{
    extern __shared__ char smc[];
    const uint32_t sb = smem_u32(smc);
    const int tid  = threadIdx.x;
    const int wid  = tid >> 5;
    const int lane = tid & 31;
    const int gid  = lane >> 2;
    const int tig  = lane & 3;
    const int wm8  = (wid >> 1) * 4;
    const int wn16 = (wid & 1) * 8;
    const int m0 = blockIdx.y * 128;
    const int n0 = blockIdx.x * 128;
    const int KT = K / 64;

    float acc[4][8][4];
#pragma unroll
    for (int i = 0; i < 4; i++)
#pragma unroll
        for (int j = 0; j < 8; j++)
#pragma unroll
            for (int r = 0; r < 4; r++) acc[i][j][r] = 0.f;

    auto load_stage = [&](int chunk, int stage) {
        const uint4* ag = (const uint4*)A + ((size_t)blockIdx.y * KT + chunk) * 1024;
        const uint4* bg = (const uint4*)Bw + ((size_t)blockIdx.x * KT + chunk) * 1024;
        const uint32_t a_s = sb + stage * 16384;
        const uint32_t b_s = sb + GM_STAGES * 16384 + stage * 16384;
#pragma unroll
        for (int it = 0; it < 8; it++) {
            int idx = it * 128 + tid;
            asm volatile("cp.async.cg.shared.global [%0], [%1], 16;"
                         :: "r"(a_s + idx * 16), "l"(ag + idx));
            asm volatile("cp.async.cg.shared.global [%0], [%1], 16;"
                         :: "r"(b_s + idx * 16), "l"(bg + idx));
        }
    };

    load_stage(0, 0);
    asm volatile("cp.async.commit_group;" ::: "memory");
    load_stage(1, 1);
    asm volatile("cp.async.commit_group;" ::: "memory");

    int cstage = 0;
    int lstage = 2;
    for (int j = 0; j < KT; j++) {
        if (j + 1 < KT) {
            asm volatile("cp.async.wait_group 1;" ::: "memory");
        } else {
            asm volatile("cp.async.wait_group 0;" ::: "memory");
        }
        __syncthreads();
        if (j + 2 < KT) {
            load_stage(j + 2, lstage);
            asm volatile("cp.async.commit_group;" ::: "memory");
        }

        const uint4* at4 = (const uint4*)(smc + cstage * 16384);
        const uint2* bt2 = (const uint2*)(smc + GM_STAGES * 16384 + cstage * 16384);

#pragma unroll
        for (int ks = 0; ks < 4; ks++) {
            uint4 afr[4];
#pragma unroll
            for (int mt = 0; mt < 4; mt++)
                afr[mt] = at4[(((wm8 + mt) * 4 + ks) << 5) + lane];
            uint2 bfr[8];
#pragma unroll
            for (int nt = 0; nt < 8; nt++)
                bfr[nt] = bt2[(((wn16 + nt) * 4 + ks) << 5) + lane];
#pragma unroll
            for (int mt = 0; mt < 4; mt++)
#pragma unroll
                for (int nt = 0; nt < 8; nt++)
                    mma_f16(acc[mt][nt],
                            (const uint32_t*)&afr[mt],
                            (const uint32_t*)&bfr[nt]);
        }
        cstage = (cstage == GM_STAGES - 1) ? 0 : cstage + 1;
        lstage = (lstage == GM_STAGES - 1) ? 0 : lstage + 1;
    }

#pragma unroll
    for (int mt = 0; mt < 4; mt++) {
        const int row = m0 + (wid >> 1) * 64 + mt * 16 + gid;
#pragma unroll
        for (int nt = 0; nt < 8; nt++) {
            const int col = n0 + (wid & 1) * 64 + nt * 8 + tig * 2;
            float2 bv = *(const float2*)(bias + col);
            float o0x = acc[mt][nt][0] + bv.x;
            float o0y = acc[mt][nt][1] + bv.y;
            float o1x = acc[mt][nt][2] + bv.x;
            float o1y = acc[mt][nt][3] + bv.y;
            if (out_half) {
                uint32_t h0 = f2h2(o0x, o0y);
                uint32_t h1 = f2h2(o1x, o1y);
                *(uint32_t*)(Ch + (size_t)row * N + col) = h0;
                *(uint32_t*)(Ch + (size_t)(row + 8) * N + col) = h1;
            } else {
                *(float2*)(C + (size_t)row * N + col) = make_float2(o0x, o0y);
                *(float2*)(C + (size_t)(row + 8) * N + col) = make_float2(o1x, o1y);
            }
        }
    }
}

// ---------------------------------------------------------------------------
// fp16 flash attention (4 warps x 32 q-rows); epilogue writes output
// directly in A-fragment-packed fp16 (feeds O-projection, no repack pass).
// ---------------------------------------------------------------------------
#define ATT_SMEM_BYTES (2 * 16384)   // 32768

__global__ __launch_bounds__(128, 2) void attn_h(
    const __half* __restrict__ qkvh, const __half* __restrict__ kvp,
    __half* __restrict__ valsp)
{
    extern __shared__ char smc[];
    const uint32_t sb = smem_u32(smc);

    const int tid  = threadIdx.x;
    const int wid  = tid >> 5;
    const int lane = tid & 31;
    const int gid  = lane >> 2;
    const int tig  = lane & 3;
    const int b  = blockIdx.z;
    const int h  = blockIdx.y;
    const int q0 = blockIdx.x * 128;

    const float qs = 0.125f * 1.4426950408889634f;

    uint32_t qf[2][4][4];
#pragma unroll
    for (int m = 0; m < 2; m++) {
        const __half* qlo = qkvh + (size_t)(b * SS + q0 + wid * 32 + m * 16 + gid) * QKV_N + h * 192;
        const __half* qhi = qlo + 8 * QKV_N;
#pragma unroll
        for (int ks = 0; ks < 4; ks++) {
            const int kb = ks * 16 + 2 * tig;
            qf[m][ks][0] = f2h2(__half2float(qlo[kb]) * qs,     __half2float(qlo[kb + 1]) * qs);
            qf[m][ks][1] = f2h2(__half2float(qhi[kb]) * qs,     __half2float(qhi[kb + 1]) * qs);
            qf[m][ks][2] = f2h2(__half2float(qlo[kb + 8]) * qs, __half2float(qlo[kb + 9]) * qs);
            qf[m][ks][3] = f2h2(__half2float(qhi[kb + 8]) * qs, __half2float(qhi[kb + 9]) * qs);
        }
    }

    const __half* kvbase = kvp + (size_t)(b * HH + h) * 32 * 8192;
    auto load_tile = [&](int kt) {
        const uint4* src = (const uint4*)(kvbase + (size_t)kt * 8192);
        const uint32_t dst = sb + (kt & 1) * 16384;
#pragma unroll
        for (int it = 0; it < 8; it++) {
            int idx = it * 128 + tid;
            asm volatile("cp.async.cg.shared.global [%0], [%1], 16;"
                         :: "r"(dst + idx * 16), "l"(src + idx));
        }
    };

    float mx[2][2], lx[2][2];
#pragma unroll
    for (int m = 0; m < 2; m++) {
        mx[m][0] = mx[m][1] = -1e30f;
        lx[m][0] = lx[m][1] = 0.f;
    }
    float oacc[2][8][4];
#pragma unroll
    for (int m = 0; m < 2; m++)
#pragma unroll
        for (int nt = 0; nt < 8; nt++)
#pragma unroll
            for (int r = 0; r < 4; r++) oacc[m][nt][r] = 0.f;

    load_tile(0);
    asm volatile("cp.async.commit_group;" ::: "memory");

    const int NT = SS / 64;
    for (int kt = 0; kt < NT; kt++) {
        asm volatile("cp.async.wait_group 0;" ::: "memory");
        __syncthreads();
        if (kt + 1 < NT) {
            load_tile(kt + 1);
            asm volatile("cp.async.commit_group;" ::: "memory");
        }

        const uint2* kp2 = (const uint2*)(smc + (kt & 1) * 16384);
        const uint2* vp2 = kp2 + 1024;

        // ---- S = Q @ K^T ----
        float sacc[2][8][4];
#pragma unroll
        for (int m = 0; m < 2; m++)
#pragma unroll
            for (int nt = 0; nt < 8; nt++)
#pragma unroll
                for (int r = 0; r < 4; r++) sacc[m][nt][r] = 0.f;

#pragma unroll
        for (int ks = 0; ks < 4; ks++) {
            uint2 kfr[8];
#pragma unroll
            for (int nt = 0; nt < 8; nt++)
                kfr[nt] = kp2[((nt * 4 + ks) << 5) + lane];
#pragma unroll
            for (int m = 0; m < 2; m++)
#pragma unroll
                for (int nt = 0; nt < 8; nt++)
                    mma_f16(sacc[m][nt], qf[m][ks], (const uint32_t*)&kfr[nt]);
        }

        // ---- online softmax + build fp16 P fragments ----
        uint32_t pf[2][4][4];
#pragma unroll
        for (int m = 0; m < 2; m++) {
            float tmax0 = -1e30f, tmax1 = -1e30f;
#pragma unroll
            for (int nt = 0; nt < 8; nt++) {
                tmax0 = fmaxf(tmax0, fmaxf(sacc[m][nt][0], sacc[m][nt][1]));
                tmax1 = fmaxf(tmax1, fmaxf(sacc[m][nt][2], sacc[m][nt][3]));
            }
            tmax0 = fmaxf(tmax0, __shfl_xor_sync(0xffffffffu, tmax0, 1));
            tmax0 = fmaxf(tmax0, __shfl_xor_sync(0xffffffffu, tmax0, 2));
            tmax1 = fmaxf(tmax1, __shfl_xor_sync(0xffffffffu, tmax1, 1));
            tmax1 = fmaxf(tmax1, __shfl_xor_sync(0xffffffffu, tmax1, 2));

            const float mn0 = fmaxf(mx[m][0], tmax0);
            const float mn1 = fmaxf(mx[m][1], tmax1);
            const float corr0 = ex2(mx[m][0] - mn0);
            const float corr1 = ex2(mx[m][1] - mn1);
            mx[m][0] = mn0;
            mx[m][1] = mn1;

            float sum0 = 0.f, sum1 = 0.f;
#pragma unroll
            for (int nt = 0; nt < 8; nt++) {
                float p0 = ex2(sacc[m][nt][0] - mn0);
                float p1 = ex2(sacc[m][nt][1] - mn0);
                float p2 = ex2(sacc[m][nt][2] - mn1);
                float p3 = ex2(sacc[m][nt][3] - mn1);
                sum0 += p0 + p1;
                sum1 += p2 + p3;
                const int j = nt >> 1;
                if ((nt & 1) == 0) {
                    pf[m][j][0] = f2h2(p0, p1);
                    pf[m][j][1] = f2h2(p2, p3);
                } else {
                    pf[m][j][2] = f2h2(p0, p1);
                    pf[m][j][3] = f2h2(p2, p3);
                }
            }
#pragma unroll
            for (int nt = 0; nt < 8; nt++) {
                oacc[m][nt][0] *= corr0;
                oacc[m][nt][1] *= corr0;
                oacc[m][nt][2] *= corr1;
                oacc[m][nt][3] *= corr1;
            }
            sum0 += __shfl_xor_sync(0xffffffffu, sum0, 1);
            sum0 += __shfl_xor_sync(0xffffffffu, sum0, 2);
            sum1 += __shfl_xor_sync(0xffffffffu, sum1, 1);
            sum1 += __shfl_xor_sync(0xffffffffu, sum1, 2);
            lx[m][0] = lx[m][0] * corr0 + sum0;
            lx[m][1] = lx[m][1] * corr1 + sum1;
        }

        // ---- O += P @ V ----
#pragma unroll
        for (int j = 0; j < 4; j++) {
            uint2 vfr[8];
#pragma unroll
            for (int nt = 0; nt < 8; nt++)
                vfr[nt] = vp2[((j * 8 + nt) << 5) + lane];
#pragma unroll
            for (int m = 0; m < 2; m++)
#pragma unroll
                for (int nt = 0; nt < 8; nt++)
                    mma_f16(oacc[m][nt], pf[m][j], (const uint32_t*)&vfr[nt]);
        }
    }

    // ---- normalize + write A-fragment-packed fp16 output ----
    {
        const size_t mtile = (size_t)(b * SS + q0) >> 7;
        uint4* o = (uint4*)(valsp + (mtile * 16 + h) * 8192);
#pragma unroll
        for (int m = 0; m < 2; m++) {
            const float inv0 = 1.f / lx[m][0];
            const float inv1 = 1.f / lx[m][1];
            const int grp = wid * 2 + m;
#pragma unroll
            for (int ks = 0; ks < 4; ks++) {
                uint4 w;
                w.x = f2h2(oacc[m][2 * ks][0] * inv0,     oacc[m][2 * ks][1] * inv0);
                w.y = f2h2(oacc[m][2 * ks][2] * inv1,     oacc[m][2 * ks][3] * inv1);
                w.z = f2h2(oacc[m][2 * ks + 1][0] * inv0, oacc[m][2 * ks + 1][1] * inv0);
                w.w = f2h2(oacc[m][2 * ks + 1][2] * inv1, oacc[m][2 * ks + 1][3] * inv1);
                o[((grp * 4 + ks) << 5) + lane] = w;
            }
        }
    }
}

// ---------------------------------------------------------------------------
// Launch
// ---------------------------------------------------------------------------
extern "C" void kernel_launch(void* const* d_in, const int* in_sizes, int n_in,
                              void* d_out, int out_size)
{
    const float* x      = (const float*)d_in[0];
    const float* w_qkv  = (const float*)d_in[1];
    const float* b_qkv  = (const float*)d_in[2];
    const float* w_o    = (const float*)d_in[3];
    const float* b_o    = (const float*)d_in[4];
    float* out = (float*)d_out;

    __half *qkvh, *xc, *valsp, *wqc, *woc, *kvp;
    cudaGetSymbolAddress((void**)&qkvh,  g_qkvh);
    cudaGetSymbolAddress((void**)&xc,    g_xc);
    cudaGetSymbolAddress((void**)&valsp, g_valsp);
    cudaGetSymbolAddress((void**)&wqc,   g_wqc);
    cudaGetSymbolAddress((void**)&woc,   g_woc);
    cudaGetSymbolAddress((void**)&kvp,   g_kvp);

    cudaFuncSetAttribute(gemm_h,
                         cudaFuncAttributeMaxDynamicSharedMemorySize,
                         GEMM_SMEM_BYTES);
    cudaFuncSetAttribute(attn_h,
                         cudaFuncAttributeMaxDynamicSharedMemorySize,
                         ATT_SMEM_BYTES);

    // 0) fragment-pack GEMM inputs into fp16
    pack_a_h<<<(M_ROWS / 128) * (DIN / 64), 256>>>(x, xc, DIN);
    pack_b_h<<<(QKV_N / 128) * (DIN / 64), 256>>>(w_qkv, wqc, DIN);
    pack_b_h<<<(DD / 128) * (DIN / 64), 256>>>(w_o, woc, DIN);

    // 1) QKV projection -> g_qkvh (fp16 row-major)
    {
        dim3 grid(QKV_N / 128, M_ROWS / 128);
        gemm_h<<<grid, 128, GEMM_SMEM_BYTES>>>(
            xc, wqc, b_qkv, nullptr, qkvh, M_ROWS, QKV_N, DIN, 1);
    }

    // 1b) fragment-pack K/V tiles
    {
        dim3 grid(SS / 64, HH, BB);
        pack_kv_h<<<grid, 256>>>(qkvh, kvp);
    }

    // 2) Attention -> g_valsp (fp16 A-frag-packed)
    {
        dim3 grid(SS / 128, HH, BB);
        attn_h<<<grid, 128, ATT_SMEM_BYTES>>>(qkvh, kvp, valsp);
    }

    // 3) O-projection -> out (fp32)
    {
        dim3 grid(DD / 128, M_ROWS / 128);
        gemm_h<<<grid, 128, GEMM_SMEM_BYTES>>>(
            valsp, woc, b_o, out, nullptr, M_ROWS, DD, DIN, 0);
    }
}